// round 10
// baseline (speedup 1.0000x reference)
#include <cuda_runtime.h>
#include <math.h>

#define NN 32768
#define EE 262144
#define FF 64
#define PSC 9
#define NF (NN*FF)
#define HS 68   // padded row stride (floats)

typedef unsigned long long u64;

// ---------------- device scratch ----------------
__device__ float g_skip_s[NF];
__device__ float g_skip_v[3*NF];
__device__ float g_sup[NF];
__device__ float g_vup[3*NF];
__device__ float g_agg_s[NF];
__device__ float g_agg_v[3*NF];
__device__ float g_w[(size_t)EE*320];   // per-edge TP path weights [E,5,64]

// ---------------- f32x2 packed-math helpers ----------------
__device__ __forceinline__ u64 pack2(float x) {
    u64 r; asm("mov.b64 %0, {%1, %1};" : "=l"(r) : "f"(x)); return r;
}
__device__ __forceinline__ u64 fma2(u64 a, u64 b, u64 c) {
    u64 d; asm("fma.rn.f32x2 %0, %1, %2, %3;" : "=l"(d) : "l"(a), "l"(b), "l"(c)); return d;
}
__device__ __forceinline__ float2 unpk(u64 a) {
    float2 f; asm("mov.b64 {%0, %1}, %2;" : "=f"(f.x), "=f"(f.y) : "l"(a)); return f;
}
__device__ __forceinline__ float silu(float x) { return x / (1.f + __expf(-x)); }

__global__ void zero_agg() {
    int stride = gridDim.x * blockDim.x;
    int t = blockIdx.x * blockDim.x + threadIdx.x;
    for (int i = t; i < NF; i += stride) g_agg_s[i] = 0.f;
    for (int i = t; i < 3*NF; i += stride) g_agg_v[i] = 0.f;
}

// ---------------- kernel A: per-species skip linear + linear_up (R8 exact) ----------------
__global__ void __launch_bounds__(512)
node_pre(const float* __restrict__ nf,
         const float* __restrict__ Wss,
         const float* __restrict__ Wsv,
         const float* __restrict__ Wus,
         const float* __restrict__ Wuv,
         const int*   __restrict__ species) {
    __shared__ float sWus[FF*FF], sWuv[FF*FF];
    __shared__ float s_sh[8][FF];
    __shared__ float v_sh[8][3*FF];
    int tid = threadIdx.x;
    for (int i = tid; i < FF*FF; i += 512) { sWus[i] = Wus[i]; sWuv[i] = Wuv[i]; }
    __syncthreads();
    int g = tid & 63, grp = tid >> 6;
    int bar = grp + 1;
    int group_id = blockIdx.x * 8 + grp;
    int totalGroups = gridDim.x * 8;
    for (int n = group_id; n < NN; n += totalGroups) {
        const float* row = nf + (size_t)n * 256;
        s_sh[grp][g]        = row[g];
        v_sh[grp][g]        = row[64 + g];
        v_sh[grp][64 + g]   = row[128 + g];
        v_sh[grp][128 + g]  = row[192 + g];
        asm volatile("bar.sync %0, 64;" :: "r"(bar) : "memory");
        int z = species[n];
        const float* wssz = Wss + z * 4096;
        const float* wsvz = Wsv + z * 4096;
        float ks = 0.f, kv0 = 0.f, kv1 = 0.f, kv2 = 0.f;
        float us = 0.f, uv0 = 0.f, uv1 = 0.f, uv2 = 0.f;
        #pragma unroll 8
        for (int f = 0; f < FF; f++) {
            float sv = s_sh[grp][f];
            float a0 = v_sh[grp][f*3], a1 = v_sh[grp][f*3+1], a2 = v_sh[grp][f*3+2];
            float w1 = __ldg(wssz + f*64 + g);
            float w2 = __ldg(wsvz + f*64 + g);
            float w3 = sWus[f*64 + g];
            float w4 = sWuv[f*64 + g];
            ks  += sv * w1; kv0 += a0 * w2; kv1 += a1 * w2; kv2 += a2 * w2;
            us  += sv * w3; uv0 += a0 * w4; uv1 += a1 * w4; uv2 += a2 * w4;
        }
        const float invZ = 0.039528471f;
        const float inv  = 0.125f;
        g_skip_s[n*64 + g]          = ks  * invZ;
        g_skip_v[0*NF + n*64 + g]   = kv0 * invZ;
        g_skip_v[1*NF + n*64 + g]   = kv1 * invZ;
        g_skip_v[2*NF + n*64 + g]   = kv2 * invZ;
        g_sup[n*64 + g]             = us  * inv;
        g_vup[0*NF + n*64 + g]      = uv0 * inv;
        g_vup[1*NF + n*64 + g]      = uv1 * inv;
        g_vup[2*NF + n*64 + g]      = uv2 * inv;
        asm volatile("bar.sync %0, 64;" :: "r"(bar) : "memory");
    }
}

// ---------------- kernel B1: radial MLP (R5 exact) ----------------
#define MLP_SMEM_FLOATS (512 + 4096 + 4096 + 20480 + 2048 + 256*HS)

__device__ __forceinline__ void kstep(const float* __restrict__ hin, int e0, int k,
                                      const float* __restrict__ wrow, u64 acc[4][4]) {
    u64 hp[4];
    #pragma unroll
    for (int ee = 0; ee < 4; ee++) hp[ee] = pack2(hin[(e0+ee)*HS + k]);
    ulonglong2 wa = *(const ulonglong2*)(wrow);
    ulonglong2 wb = *(const ulonglong2*)(wrow + 4);
    #pragma unroll
    for (int ee = 0; ee < 4; ee++) {
        acc[0][ee] = fma2(hp[ee], wa.x, acc[0][ee]);
        acc[1][ee] = fma2(hp[ee], wa.y, acc[1][ee]);
        acc[2][ee] = fma2(hp[ee], wb.x, acc[2][ee]);
        acc[3][ee] = fma2(hp[ee], wb.y, acc[3][ee]);
    }
}

__device__ __forceinline__ void zacc(u64 acc[4][4]) {
    #pragma unroll
    for (int gp = 0; gp < 4; gp++)
        #pragma unroll
        for (int ee = 0; ee < 4; ee++) acc[gp][ee] = 0ull;
}

__device__ __forceinline__ void write_silu(u64 acc[4][4], float* h, int e0, int g0, float scale) {
    #pragma unroll
    for (int ee = 0; ee < 4; ee++) {
        float2 a = unpk(acc[0][ee]), b = unpk(acc[1][ee]);
        float2 c = unpk(acc[2][ee]), d = unpk(acc[3][ee]);
        float4 lo = make_float4(silu(a.x*scale), silu(a.y*scale), silu(b.x*scale), silu(b.y*scale));
        float4 hi = make_float4(silu(c.x*scale), silu(c.y*scale), silu(d.x*scale), silu(d.y*scale));
        *(float4*)(h + (e0+ee)*HS + g0)     = lo;
        *(float4*)(h + (e0+ee)*HS + g0 + 4) = hi;
    }
}

__global__ void __launch_bounds__(512)
mlp_kernel(const float* __restrict__ re,
           const float* __restrict__ W1,
           const float* __restrict__ W2,
           const float* __restrict__ W3,
           const float* __restrict__ W4) {
    extern __shared__ float sm[];
    float* sW1 = sm;
    float* sW2 = sW1 + 512;
    float* sW3 = sW2 + 4096;
    float* sW4 = sW3 + 4096;
    float* sRE = sW4 + 20480;
    float* h   = sRE + 2048;
    int tid = threadIdx.x;
    for (int i = tid; i < 512;   i += 512) sW1[i] = W1[i];
    for (int i = tid; i < 4096;  i += 512) { sW2[i] = W2[i]; sW3[i] = W3[i]; }
    for (int i = tid; i < 20480; i += 512) sW4[i] = W4[i];

    int e_base = blockIdx.x * 256;
    for (int i = tid; i < 2048; i += 512) sRE[i] = re[(size_t)e_base*8 + i];
    __syncthreads();

    int cj = tid & 7, ei = tid >> 3;
    int g0 = cj * 8, e0 = ei * 4;

    u64 acc[4][4];

    zacc(acc);
    #pragma unroll
    for (int k = 0; k < 8; k++) {
        u64 hp[4];
        #pragma unroll
        for (int ee = 0; ee < 4; ee++) hp[ee] = pack2(sRE[(e0+ee)*8 + k]);
        ulonglong2 wa = *(const ulonglong2*)(sW1 + k*64 + g0);
        ulonglong2 wb = *(const ulonglong2*)(sW1 + k*64 + g0 + 4);
        #pragma unroll
        for (int ee = 0; ee < 4; ee++) {
            acc[0][ee] = fma2(hp[ee], wa.x, acc[0][ee]);
            acc[1][ee] = fma2(hp[ee], wa.y, acc[1][ee]);
            acc[2][ee] = fma2(hp[ee], wb.x, acc[2][ee]);
            acc[3][ee] = fma2(hp[ee], wb.y, acc[3][ee]);
        }
    }
    write_silu(acc, h, e0, g0, 0.35355339f);
    __syncthreads();

    zacc(acc);
    #pragma unroll 4
    for (int k = 0; k < 64; k++) kstep(h, e0, k, sW2 + k*64 + g0, acc);
    __syncthreads();
    write_silu(acc, h, e0, g0, 0.125f);
    __syncthreads();

    zacc(acc);
    #pragma unroll 4
    for (int k = 0; k < 64; k++) kstep(h, e0, k, sW3 + k*64 + g0, acc);
    __syncthreads();
    write_silu(acc, h, e0, g0, 0.125f);
    __syncthreads();

    #pragma unroll
    for (int p = 0; p < 5; p++) {
        zacc(acc);
        #pragma unroll 4
        for (int k = 0; k < 64; k++) kstep(h, e0, k, sW4 + k*320 + p*64 + g0, acc);
        #pragma unroll
        for (int ee = 0; ee < 4; ee++) {
            float2 a = unpk(acc[0][ee]), b = unpk(acc[1][ee]);
            float2 c = unpk(acc[2][ee]), d = unpk(acc[3][ee]);
            float* dst = g_w + (size_t)(e_base + e0 + ee)*320 + p*64 + g0;
            *(float4*)dst       = make_float4(a.x*0.125f, a.y*0.125f, b.x*0.125f, b.y*0.125f);
            *(float4*)(dst + 4) = make_float4(c.x*0.125f, c.y*0.125f, d.x*0.125f, d.y*0.125f);
        }
    }
}

// ---------------- kernel B2: tensor product + scatter (R5 exact) ----------------
__global__ void tp_scatter(const float* __restrict__ vectors,
                           const int* __restrict__ senders,
                           const int* __restrict__ receivers) {
    int t = blockIdx.x * 256 + threadIdx.x;
    int e = t >> 6, g = t & 63;
    float vx = __ldg(vectors + e*3), vy = __ldg(vectors + e*3 + 1), vz = __ldg(vectors + e*3 + 2);
    float rn = 1.f / (sqrtf(vx*vx + vy*vy + vz*vz) + 1e-9f);
    float y0 = vx * rn, y1 = vy * rn, y2 = vz * rn;

    const float* wrow = g_w + (size_t)e*320 + g;
    float w0  = wrow[0];
    float w1a = wrow[64];
    float w2a = wrow[128];
    float w3a = wrow[192];
    float w4a = wrow[256];

    int sn = __ldg(senders + e), rc = __ldg(receivers + e);
    float ss = g_sup[sn*64 + g];
    float b0 = g_vup[0*NF + sn*64 + g];
    float b1 = g_vup[1*NF + sn*64 + g];
    float b2 = g_vup[2*NF + sn*64 + g];
    float dot = b0*y0 + b1*y1 + b2*y2;
    float c0 = b1*y2 - b2*y1;
    float c1 = b2*y0 - b0*y2;
    float c2 = b0*y1 - b1*y0;
    const float is2 = 0.70710678f;
    float ms  = (w0*ss + w3a*dot) * 0.25f;
    float mv0 = (w1a*y0 + w2a*b0 + w4a*c0*is2) * 0.25f;
    float mv1 = (w1a*y1 + w2a*b1 + w4a*c1*is2) * 0.25f;
    float mv2 = (w1a*y2 + w2a*b2 + w4a*c2*is2) * 0.25f;
    atomicAdd(&g_agg_s[rc*64 + g], ms);
    atomicAdd(&g_agg_v[0*NF + rc*64 + g], mv0);
    atomicAdd(&g_agg_v[1*NF + rc*64 + g], mv1);
    atomicAdd(&g_agg_v[2*NF + rc*64 + g], mv2);
}

// ---------------- kernel C: node_post as f32x2 GEMM over 64-node tiles ----------------
// 512 thr; thread (cj = tid&7 -> 8 channels, ei = tid>>3 -> node). Rows r = ei*4 + comp.
#define POSTG_SMEM_FLOATS (4*4096 + 256*HS + 512 + 64)
__global__ void __launch_bounds__(512)
node_post_g(const float* __restrict__ Wds,
            const float* __restrict__ Wdv,
            const float* __restrict__ Wsc,
            const float* __restrict__ Wps,
            const float* __restrict__ Wpv,
            const float* __restrict__ Wout,
            const int*   __restrict__ species,
            float* __restrict__ out) {
    extern __shared__ float sm[];
    float* sWds = sm;
    float* sWdv = sm + 4096;
    float* sWps = sm + 8192;
    float* sWpv = sm + 12288;
    float* h    = sm + 16384;      // [256][HS]
    float* red  = h + 256*HS;      // [64][8]
    float* sWo  = red + 512;       // [64]
    int tid = threadIdx.x;
    for (int i = tid; i < 4096; i += 512) {
        sWds[i] = Wds[i]; sWdv[i] = Wdv[i]; sWps[i] = Wps[i]; sWpv[i] = Wpv[i];
    }
    if (tid < 64) sWo[tid] = Wout[tid];

    int cj = tid & 7, ei = tid >> 3;
    int g0 = cj * 8;
    int n = blockIdx.x * 64 + ei;
    int r0 = ei * 4;

    // stage 1: load aggregates into h rows (s, v0, v1, v2)
    {
        const float* src = g_agg_s + n*64 + g0;
        *(float4*)(h + r0*HS + g0)     = *(const float4*)(src);
        *(float4*)(h + r0*HS + g0 + 4) = *(const float4*)(src + 4);
        #pragma unroll
        for (int c = 0; c < 3; c++) {
            const float* sv = g_agg_v + c*NF + n*64 + g0;
            *(float4*)(h + (r0+1+c)*HS + g0)     = *(const float4*)(sv);
            *(float4*)(h + (r0+1+c)*HS + g0 + 4) = *(const float4*)(sv + 4);
        }
    }
    __syncthreads();

    float sd[8], vd0[8], vd1[8], vd2[8];

    // GEMM1: linear_down
    {
        u64 acc[4][4];
        #pragma unroll
        for (int gp = 0; gp < 4; gp++)
            #pragma unroll
            for (int c = 0; c < 4; c++) acc[gp][c] = 0ull;
        #pragma unroll 4
        for (int k = 0; k < 64; k++) {
            u64 hp0 = pack2(h[r0*HS + k]);
            u64 hp1 = pack2(h[(r0+1)*HS + k]);
            u64 hp2 = pack2(h[(r0+2)*HS + k]);
            u64 hp3 = pack2(h[(r0+3)*HS + k]);
            ulonglong2 da = *(const ulonglong2*)(sWds + k*64 + g0);
            ulonglong2 db = *(const ulonglong2*)(sWds + k*64 + g0 + 4);
            ulonglong2 va = *(const ulonglong2*)(sWdv + k*64 + g0);
            ulonglong2 vb = *(const ulonglong2*)(sWdv + k*64 + g0 + 4);
            acc[0][0] = fma2(hp0, da.x, acc[0][0]); acc[1][0] = fma2(hp0, da.y, acc[1][0]);
            acc[2][0] = fma2(hp0, db.x, acc[2][0]); acc[3][0] = fma2(hp0, db.y, acc[3][0]);
            acc[0][1] = fma2(hp1, va.x, acc[0][1]); acc[1][1] = fma2(hp1, va.y, acc[1][1]);
            acc[2][1] = fma2(hp1, vb.x, acc[2][1]); acc[3][1] = fma2(hp1, vb.y, acc[3][1]);
            acc[0][2] = fma2(hp2, va.x, acc[0][2]); acc[1][2] = fma2(hp2, va.y, acc[1][2]);
            acc[2][2] = fma2(hp2, vb.x, acc[2][2]); acc[3][2] = fma2(hp2, vb.y, acc[3][2]);
            acc[0][3] = fma2(hp3, va.x, acc[0][3]); acc[1][3] = fma2(hp3, va.y, acc[1][3]);
            acc[2][3] = fma2(hp3, vb.x, acc[2][3]); acc[3][3] = fma2(hp3, vb.y, acc[3][3]);
        }
        #pragma unroll
        for (int gp = 0; gp < 4; gp++) {
            float2 t0 = unpk(acc[gp][0]); sd[gp*2] = t0.x*0.125f; sd[gp*2+1] = t0.y*0.125f;
            float2 t1 = unpk(acc[gp][1]); vd0[gp*2] = t1.x*0.125f; vd0[gp*2+1] = t1.y*0.125f;
            float2 t2 = unpk(acc[gp][2]); vd1[gp*2] = t2.x*0.125f; vd1[gp*2+1] = t2.y*0.125f;
            float2 t3 = unpk(acc[gp][3]); vd2[gp*2] = t3.x*0.125f; vd2[gp*2+1] = t3.y*0.125f;
        }
    }

    // symmetric contraction (registers only), results back into sd/vd arrays
    {
        int z = __ldg(species + n);
        const float* wz = Wsc + z * (PSC*64) + g0;
        #pragma unroll
        for (int j = 0; j < 8; j++) {
            float q0 = __ldg(wz + j),       q1 = __ldg(wz + 64 + j),  q2 = __ldg(wz + 128 + j);
            float q3 = __ldg(wz + 192 + j), q4 = __ldg(wz + 256 + j), q5 = __ldg(wz + 320 + j);
            float q6 = __ldg(wz + 384 + j), q7 = __ldg(wz + 448 + j), q8 = __ldg(wz + 512 + j);
            float s1 = sd[j];
            float vn2 = vd0[j]*vd0[j] + vd1[j]*vd1[j] + vd2[j]*vd2[j];
            float s2 = s1*s1;
            float sout = q0*s1 + q1*s2 + q2*vn2 + q3*s2*s1 + q4*s1*vn2;
            float gv   = q5 + q6*s1 + q7*s2 + q8*vn2;
            sd[j]  = sout;
            vd0[j] *= gv; vd1[j] *= gv; vd2[j] *= gv;
        }
    }
    __syncthreads();   // all GEMM1 reads of h complete before overwrite

    // write back to h
    *(float4*)(h + r0*HS + g0)         = make_float4(sd[0], sd[1], sd[2], sd[3]);
    *(float4*)(h + r0*HS + g0 + 4)     = make_float4(sd[4], sd[5], sd[6], sd[7]);
    *(float4*)(h + (r0+1)*HS + g0)     = make_float4(vd0[0], vd0[1], vd0[2], vd0[3]);
    *(float4*)(h + (r0+1)*HS + g0 + 4) = make_float4(vd0[4], vd0[5], vd0[6], vd0[7]);
    *(float4*)(h + (r0+2)*HS + g0)     = make_float4(vd1[0], vd1[1], vd1[2], vd1[3]);
    *(float4*)(h + (r0+2)*HS + g0 + 4) = make_float4(vd1[4], vd1[5], vd1[6], vd1[7]);
    *(float4*)(h + (r0+3)*HS + g0)     = make_float4(vd2[0], vd2[1], vd2[2], vd2[3]);
    *(float4*)(h + (r0+3)*HS + g0 + 4) = make_float4(vd2[4], vd2[5], vd2[6], vd2[7]);
    __syncthreads();

    // GEMM2: linear_post
    {
        u64 acc[4][4];
        #pragma unroll
        for (int gp = 0; gp < 4; gp++)
            #pragma unroll
            for (int c = 0; c < 4; c++) acc[gp][c] = 0ull;
        #pragma unroll 4
        for (int k = 0; k < 64; k++) {
            u64 hp0 = pack2(h[r0*HS + k]);
            u64 hp1 = pack2(h[(r0+1)*HS + k]);
            u64 hp2 = pack2(h[(r0+2)*HS + k]);
            u64 hp3 = pack2(h[(r0+3)*HS + k]);
            ulonglong2 da = *(const ulonglong2*)(sWps + k*64 + g0);
            ulonglong2 db = *(const ulonglong2*)(sWps + k*64 + g0 + 4);
            ulonglong2 va = *(const ulonglong2*)(sWpv + k*64 + g0);
            ulonglong2 vb = *(const ulonglong2*)(sWpv + k*64 + g0 + 4);
            acc[0][0] = fma2(hp0, da.x, acc[0][0]); acc[1][0] = fma2(hp0, da.y, acc[1][0]);
            acc[2][0] = fma2(hp0, db.x, acc[2][0]); acc[3][0] = fma2(hp0, db.y, acc[3][0]);
            acc[0][1] = fma2(hp1, va.x, acc[0][1]); acc[1][1] = fma2(hp1, va.y, acc[1][1]);
            acc[2][1] = fma2(hp1, vb.x, acc[2][1]); acc[3][1] = fma2(hp1, vb.y, acc[3][1]);
            acc[0][2] = fma2(hp2, va.x, acc[0][2]); acc[1][2] = fma2(hp2, va.y, acc[1][2]);
            acc[2][2] = fma2(hp2, vb.x, acc[2][2]); acc[3][2] = fma2(hp2, vb.y, acc[3][2]);
            acc[0][3] = fma2(hp3, va.x, acc[0][3]); acc[1][3] = fma2(hp3, va.y, acc[1][3]);
            acc[2][3] = fma2(hp3, vb.x, acc[2][3]); acc[3][3] = fma2(hp3, vb.y, acc[3][3]);
        }
        #pragma unroll
        for (int gp = 0; gp < 4; gp++) {
            float2 t0 = unpk(acc[gp][0]); sd[gp*2] = t0.x*0.125f; sd[gp*2+1] = t0.y*0.125f;
            float2 t1 = unpk(acc[gp][1]); vd0[gp*2] = t1.x*0.125f; vd0[gp*2+1] = t1.y*0.125f;
            float2 t2 = unpk(acc[gp][2]); vd1[gp*2] = t2.x*0.125f; vd1[gp*2+1] = t2.y*0.125f;
            float2 t3 = unpk(acc[gp][3]); vd2[gp*2] = t3.x*0.125f; vd2[gp*2+1] = t3.y*0.125f;
        }
    }

    // skip connection (vectorized global loads)
    {
        const float* ks  = g_skip_s + n*64 + g0;
        float4 a = *(const float4*)(ks), b = *(const float4*)(ks + 4);
        sd[0]+=a.x; sd[1]+=a.y; sd[2]+=a.z; sd[3]+=a.w;
        sd[4]+=b.x; sd[5]+=b.y; sd[6]+=b.z; sd[7]+=b.w;
        const float* k0 = g_skip_v + 0*NF + n*64 + g0;
        a = *(const float4*)(k0); b = *(const float4*)(k0 + 4);
        vd0[0]+=a.x; vd0[1]+=a.y; vd0[2]+=a.z; vd0[3]+=a.w;
        vd0[4]+=b.x; vd0[5]+=b.y; vd0[6]+=b.z; vd0[7]+=b.w;
        const float* k1 = g_skip_v + 1*NF + n*64 + g0;
        a = *(const float4*)(k1); b = *(const float4*)(k1 + 4);
        vd1[0]+=a.x; vd1[1]+=a.y; vd1[2]+=a.z; vd1[3]+=a.w;
        vd1[4]+=b.x; vd1[5]+=b.y; vd1[6]+=b.z; vd1[7]+=b.w;
        const float* k2 = g_skip_v + 2*NF + n*64 + g0;
        a = *(const float4*)(k2); b = *(const float4*)(k2 + 4);
        vd2[0]+=a.x; vd2[1]+=a.y; vd2[2]+=a.z; vd2[3]+=a.w;
        vd2[4]+=b.x; vd2[5]+=b.y; vd2[6]+=b.z; vd2[7]+=b.w;
    }

    // outputs: merged row
    {
        float* mrow = out + NN + (size_t)n * 256;
        *(float4*)(mrow + g0)     = make_float4(sd[0], sd[1], sd[2], sd[3]);
        *(float4*)(mrow + g0 + 4) = make_float4(sd[4], sd[5], sd[6], sd[7]);
        #pragma unroll
        for (int j = 0; j < 8; j++) {
            int g = g0 + j;
            mrow[64 + g*3]     = vd0[j];
            mrow[64 + g*3 + 1] = vd1[j];
            mrow[64 + g*3 + 2] = vd2[j];
        }
    }

    // readout reduction
    {
        float part = 0.f;
        #pragma unroll
        for (int j = 0; j < 8; j++) part += sd[j] * sWo[g0 + j];
        red[ei*8 + cj] = part;
        __syncthreads();
        if (cj == 0) {
            float t2 = red[ei*8] + red[ei*8+1] + red[ei*8+2] + red[ei*8+3]
                     + red[ei*8+4] + red[ei*8+5] + red[ei*8+6] + red[ei*8+7];
            out[n] = t2 * 0.125f;
        }
    }
}

// ---------------- launch ----------------
extern "C" void kernel_launch(void* const* d_in, const int* in_sizes, int n_in,
                              void* d_out, int out_size) {
    const float* vectors    = (const float*)d_in[0];
    const float* node_feats = (const float*)d_in[1];
    const float* re         = (const float*)d_in[2];
    const float* Wss        = (const float*)d_in[3];
    const float* Wsv        = (const float*)d_in[4];
    const float* Wus        = (const float*)d_in[5];
    const float* Wuv        = (const float*)d_in[6];
    const float* W1         = (const float*)d_in[7];
    const float* W2         = (const float*)d_in[8];
    const float* W3         = (const float*)d_in[9];
    const float* W4         = (const float*)d_in[10];
    const float* Wds        = (const float*)d_in[11];
    const float* Wdv        = (const float*)d_in[12];
    const float* Wsc        = (const float*)d_in[13];
    const float* Wps        = (const float*)d_in[14];
    const float* Wpv        = (const float*)d_in[15];
    const float* Wout       = (const float*)d_in[16];
    const int*   species    = (const int*)d_in[17];
    const int*   senders    = (const int*)d_in[18];
    const int*   receivers  = (const int*)d_in[19];
    float* out = (float*)d_out;

    const int MLP_SMEM   = MLP_SMEM_FLOATS * 4;    // 195584 B
    const int POSTG_SMEM = POSTG_SMEM_FLOATS * 4;  // 137472 B
    cudaFuncSetAttribute(mlp_kernel,  cudaFuncAttributeMaxDynamicSharedMemorySize, MLP_SMEM);
    cudaFuncSetAttribute(node_post_g, cudaFuncAttributeMaxDynamicSharedMemorySize, POSTG_SMEM);

    zero_agg<<<2048, 256>>>();
    node_pre<<<444, 512>>>(node_feats, Wss, Wsv, Wus, Wuv, species);
    mlp_kernel<<<EE/256, 512, MLP_SMEM>>>(re, W1, W2, W3, W4);
    tp_scatter<<<EE*64/256, 256>>>(vectors, senders, receivers);
    node_post_g<<<NN/64, 512, POSTG_SMEM>>>(Wds, Wdv, Wsc, Wps, Wpv, Wout, species, out);
}

// round 11
// speedup vs baseline: 1.0281x; 1.0281x over previous
#include <cuda_runtime.h>
#include <math.h>

#define NN 32768
#define EE 262144
#define FF 64
#define PSC 9
#define NF (NN*FF)
#define HS 68   // padded row stride (floats)

typedef unsigned long long u64;

// ---------------- device scratch ----------------
__device__ float g_skip_s[NF];
__device__ float g_skip_v[3*NF];
__device__ float g_sup[NF];
__device__ float g_vup[3*NF];
__device__ float g_agg_s[NF];
__device__ float g_agg_v[3*NF];
__device__ float g_w[(size_t)EE*320];   // per-edge TP path weights [E,5,64]

// ---------------- f32x2 packed-math helpers ----------------
__device__ __forceinline__ u64 pack2(float x) {
    u64 r; asm("mov.b64 %0, {%1, %1};" : "=l"(r) : "f"(x)); return r;
}
__device__ __forceinline__ u64 fma2(u64 a, u64 b, u64 c) {
    u64 d; asm("fma.rn.f32x2 %0, %1, %2, %3;" : "=l"(d) : "l"(a), "l"(b), "l"(c)); return d;
}
__device__ __forceinline__ float2 unpk(u64 a) {
    float2 f; asm("mov.b64 {%0, %1}, %2;" : "=f"(f.x), "=f"(f.y) : "l"(a)); return f;
}
__device__ __forceinline__ float silu(float x) { return x / (1.f + __expf(-x)); }

__global__ void zero_agg() {
    int stride = gridDim.x * blockDim.x;
    int t = blockIdx.x * blockDim.x + threadIdx.x;
    for (int i = t; i < NF; i += stride) g_agg_s[i] = 0.f;
    for (int i = t; i < 3*NF; i += stride) g_agg_v[i] = 0.f;
}

// ---------------- kernel A: per-species skip linear + linear_up (R8 exact) ----------------
__global__ void __launch_bounds__(512)
node_pre(const float* __restrict__ nf,
         const float* __restrict__ Wss,
         const float* __restrict__ Wsv,
         const float* __restrict__ Wus,
         const float* __restrict__ Wuv,
         const int*   __restrict__ species) {
    __shared__ float sWus[FF*FF], sWuv[FF*FF];
    __shared__ float s_sh[8][FF];
    __shared__ float v_sh[8][3*FF];
    int tid = threadIdx.x;
    for (int i = tid; i < FF*FF; i += 512) { sWus[i] = Wus[i]; sWuv[i] = Wuv[i]; }
    __syncthreads();
    int g = tid & 63, grp = tid >> 6;
    int bar = grp + 1;
    int group_id = blockIdx.x * 8 + grp;
    int totalGroups = gridDim.x * 8;
    for (int n = group_id; n < NN; n += totalGroups) {
        const float* row = nf + (size_t)n * 256;
        s_sh[grp][g]        = row[g];
        v_sh[grp][g]        = row[64 + g];
        v_sh[grp][64 + g]   = row[128 + g];
        v_sh[grp][128 + g]  = row[192 + g];
        asm volatile("bar.sync %0, 64;" :: "r"(bar) : "memory");
        int z = species[n];
        const float* wssz = Wss + z * 4096;
        const float* wsvz = Wsv + z * 4096;
        float ks = 0.f, kv0 = 0.f, kv1 = 0.f, kv2 = 0.f;
        float us = 0.f, uv0 = 0.f, uv1 = 0.f, uv2 = 0.f;
        #pragma unroll 8
        for (int f = 0; f < FF; f++) {
            float sv = s_sh[grp][f];
            float a0 = v_sh[grp][f*3], a1 = v_sh[grp][f*3+1], a2 = v_sh[grp][f*3+2];
            float w1 = __ldg(wssz + f*64 + g);
            float w2 = __ldg(wsvz + f*64 + g);
            float w3 = sWus[f*64 + g];
            float w4 = sWuv[f*64 + g];
            ks  += sv * w1; kv0 += a0 * w2; kv1 += a1 * w2; kv2 += a2 * w2;
            us  += sv * w3; uv0 += a0 * w4; uv1 += a1 * w4; uv2 += a2 * w4;
        }
        const float invZ = 0.039528471f;
        const float inv  = 0.125f;
        g_skip_s[n*64 + g]          = ks  * invZ;
        g_skip_v[0*NF + n*64 + g]   = kv0 * invZ;
        g_skip_v[1*NF + n*64 + g]   = kv1 * invZ;
        g_skip_v[2*NF + n*64 + g]   = kv2 * invZ;
        g_sup[n*64 + g]             = us  * inv;
        g_vup[0*NF + n*64 + g]      = uv0 * inv;
        g_vup[1*NF + n*64 + g]      = uv1 * inv;
        g_vup[2*NF + n*64 + g]      = uv2 * inv;
        asm volatile("bar.sync %0, 64;" :: "r"(bar) : "memory");
    }
}

// ---------------- kernel B1: radial MLP (R5 core, chunked) ----------------
#define MLP_SMEM_FLOATS (512 + 4096 + 4096 + 20480 + 2048 + 256*HS)

__device__ __forceinline__ void kstep(const float* __restrict__ hin, int e0, int k,
                                      const float* __restrict__ wrow, u64 acc[4][4]) {
    u64 hp[4];
    #pragma unroll
    for (int ee = 0; ee < 4; ee++) hp[ee] = pack2(hin[(e0+ee)*HS + k]);
    ulonglong2 wa = *(const ulonglong2*)(wrow);
    ulonglong2 wb = *(const ulonglong2*)(wrow + 4);
    #pragma unroll
    for (int ee = 0; ee < 4; ee++) {
        acc[0][ee] = fma2(hp[ee], wa.x, acc[0][ee]);
        acc[1][ee] = fma2(hp[ee], wa.y, acc[1][ee]);
        acc[2][ee] = fma2(hp[ee], wb.x, acc[2][ee]);
        acc[3][ee] = fma2(hp[ee], wb.y, acc[3][ee]);
    }
}

__device__ __forceinline__ void zacc(u64 acc[4][4]) {
    #pragma unroll
    for (int gp = 0; gp < 4; gp++)
        #pragma unroll
        for (int ee = 0; ee < 4; ee++) acc[gp][ee] = 0ull;
}

__device__ __forceinline__ void write_silu(u64 acc[4][4], float* h, int e0, int g0, float scale) {
    #pragma unroll
    for (int ee = 0; ee < 4; ee++) {
        float2 a = unpk(acc[0][ee]), b = unpk(acc[1][ee]);
        float2 c = unpk(acc[2][ee]), d = unpk(acc[3][ee]);
        float4 lo = make_float4(silu(a.x*scale), silu(a.y*scale), silu(b.x*scale), silu(b.y*scale));
        float4 hi = make_float4(silu(c.x*scale), silu(c.y*scale), silu(d.x*scale), silu(d.y*scale));
        *(float4*)(h + (e0+ee)*HS + g0)     = lo;
        *(float4*)(h + (e0+ee)*HS + g0 + 4) = hi;
    }
}

__global__ void __launch_bounds__(512)
mlp_kernel(const float* __restrict__ re,
           const float* __restrict__ W1,
           const float* __restrict__ W2,
           const float* __restrict__ W3,
           const float* __restrict__ W4,
           int block_base) {
    extern __shared__ float sm[];
    float* sW1 = sm;
    float* sW2 = sW1 + 512;
    float* sW3 = sW2 + 4096;
    float* sW4 = sW3 + 4096;
    float* sRE = sW4 + 20480;
    float* h   = sRE + 2048;
    int tid = threadIdx.x;
    for (int i = tid; i < 512;   i += 512) sW1[i] = W1[i];
    for (int i = tid; i < 4096;  i += 512) { sW2[i] = W2[i]; sW3[i] = W3[i]; }
    for (int i = tid; i < 20480; i += 512) sW4[i] = W4[i];

    int e_base = (block_base + blockIdx.x) * 256;
    for (int i = tid; i < 2048; i += 512) sRE[i] = re[(size_t)e_base*8 + i];
    __syncthreads();

    int cj = tid & 7, ei = tid >> 3;
    int g0 = cj * 8, e0 = ei * 4;

    u64 acc[4][4];

    zacc(acc);
    #pragma unroll
    for (int k = 0; k < 8; k++) {
        u64 hp[4];
        #pragma unroll
        for (int ee = 0; ee < 4; ee++) hp[ee] = pack2(sRE[(e0+ee)*8 + k]);
        ulonglong2 wa = *(const ulonglong2*)(sW1 + k*64 + g0);
        ulonglong2 wb = *(const ulonglong2*)(sW1 + k*64 + g0 + 4);
        #pragma unroll
        for (int ee = 0; ee < 4; ee++) {
            acc[0][ee] = fma2(hp[ee], wa.x, acc[0][ee]);
            acc[1][ee] = fma2(hp[ee], wa.y, acc[1][ee]);
            acc[2][ee] = fma2(hp[ee], wb.x, acc[2][ee]);
            acc[3][ee] = fma2(hp[ee], wb.y, acc[3][ee]);
        }
    }
    write_silu(acc, h, e0, g0, 0.35355339f);
    __syncthreads();

    zacc(acc);
    #pragma unroll 4
    for (int k = 0; k < 64; k++) kstep(h, e0, k, sW2 + k*64 + g0, acc);
    __syncthreads();
    write_silu(acc, h, e0, g0, 0.125f);
    __syncthreads();

    zacc(acc);
    #pragma unroll 4
    for (int k = 0; k < 64; k++) kstep(h, e0, k, sW3 + k*64 + g0, acc);
    __syncthreads();
    write_silu(acc, h, e0, g0, 0.125f);
    __syncthreads();

    #pragma unroll
    for (int p = 0; p < 5; p++) {
        zacc(acc);
        #pragma unroll 4
        for (int k = 0; k < 64; k++) kstep(h, e0, k, sW4 + k*320 + p*64 + g0, acc);
        #pragma unroll
        for (int ee = 0; ee < 4; ee++) {
            float2 a = unpk(acc[0][ee]), b = unpk(acc[1][ee]);
            float2 c = unpk(acc[2][ee]), d = unpk(acc[3][ee]);
            float* dst = g_w + (size_t)(e_base + e0 + ee)*320 + p*64 + g0;
            *(float4*)dst       = make_float4(a.x*0.125f, a.y*0.125f, b.x*0.125f, b.y*0.125f);
            *(float4*)(dst + 4) = make_float4(c.x*0.125f, c.y*0.125f, d.x*0.125f, d.y*0.125f);
        }
    }
}

// ---------------- kernel B2: tensor product + scatter (chunked) ----------------
__global__ void tp_scatter(const float* __restrict__ vectors,
                           const int* __restrict__ senders,
                           const int* __restrict__ receivers,
                           int edge_base) {
    int t = blockIdx.x * 256 + threadIdx.x;
    int e = edge_base + (t >> 6);
    int g = t & 63;
    float vx = __ldg(vectors + e*3), vy = __ldg(vectors + e*3 + 1), vz = __ldg(vectors + e*3 + 2);
    float rn = 1.f / (sqrtf(vx*vx + vy*vy + vz*vz) + 1e-9f);
    float y0 = vx * rn, y1 = vy * rn, y2 = vz * rn;

    const float* wrow = g_w + (size_t)e*320 + g;
    float w0  = wrow[0];
    float w1a = wrow[64];
    float w2a = wrow[128];
    float w3a = wrow[192];
    float w4a = wrow[256];

    int sn = __ldg(senders + e), rc = __ldg(receivers + e);
    float ss = g_sup[sn*64 + g];
    float b0 = g_vup[0*NF + sn*64 + g];
    float b1 = g_vup[1*NF + sn*64 + g];
    float b2 = g_vup[2*NF + sn*64 + g];
    float dot = b0*y0 + b1*y1 + b2*y2;
    float c0 = b1*y2 - b2*y1;
    float c1 = b2*y0 - b0*y2;
    float c2 = b0*y1 - b1*y0;
    const float is2 = 0.70710678f;
    float ms  = (w0*ss + w3a*dot) * 0.25f;
    float mv0 = (w1a*y0 + w2a*b0 + w4a*c0*is2) * 0.25f;
    float mv1 = (w1a*y1 + w2a*b1 + w4a*c1*is2) * 0.25f;
    float mv2 = (w1a*y2 + w2a*b2 + w4a*c2*is2) * 0.25f;
    atomicAdd(&g_agg_s[rc*64 + g], ms);
    atomicAdd(&g_agg_v[0*NF + rc*64 + g], mv0);
    atomicAdd(&g_agg_v[1*NF + rc*64 + g], mv1);
    atomicAdd(&g_agg_v[2*NF + rc*64 + g], mv2);
}

// ---------------- kernel C: node_post (R8 exact, 512 thr) ----------------
#define POST_SMEM_FLOATS (4*4096 + 8*576)
__global__ void __launch_bounds__(512)
node_post(const float* __restrict__ Wds,
          const float* __restrict__ Wdv,
          const float* __restrict__ Wsc,
          const float* __restrict__ Wps,
          const float* __restrict__ Wpv,
          const float* __restrict__ Wout,
          const int*   __restrict__ species,
          float* __restrict__ out) {
    extern __shared__ float sm[];
    float* sWds = sm;
    float* sWdv = sm + 4096;
    float* sWps = sm + 8192;
    float* sWpv = sm + 12288;
    float* buf  = sm + 16384;
    int tid = threadIdx.x;
    for (int i = tid; i < 4096; i += 512) {
        sWds[i] = Wds[i]; sWdv[i] = Wdv[i]; sWps[i] = Wps[i]; sWpv[i] = Wpv[i];
    }
    __syncthreads();
    int g = tid & 63, grp = tid >> 6, bar = grp + 1;
    float* ags = buf + grp * 576;
    float* agv = ags + 64;
    float* so  = agv + 192;
    float* vo  = so + 64;
    float* red = vo + 192;
    int group_id = blockIdx.x * 8 + grp;
    int totalGroups = gridDim.x * 8;
    for (int n = group_id; n < NN; n += totalGroups) {
        ags[g]       = g_agg_s[n*64 + g];
        agv[g]       = g_agg_v[0*NF + n*64 + g];
        agv[64 + g]  = g_agg_v[1*NF + n*64 + g];
        agv[128 + g] = g_agg_v[2*NF + n*64 + g];
        asm volatile("bar.sync %0, 64;" :: "r"(bar) : "memory");

        float sd = 0.f, vd0 = 0.f, vd1 = 0.f, vd2 = 0.f;
        #pragma unroll 8
        for (int f = 0; f < 64; f++) {
            float a  = ags[f];
            float a0 = agv[f], a1 = agv[64 + f], a2 = agv[128 + f];
            float w1 = sWds[f*64 + g], w2 = sWdv[f*64 + g];
            sd += a * w1; vd0 += a0 * w2; vd1 += a1 * w2; vd2 += a2 * w2;
        }
        sd *= 0.125f; vd0 *= 0.125f; vd1 *= 0.125f; vd2 *= 0.125f;

        int z = species[n];
        const float* wz = Wsc + z * (PSC*64) + g;
        float q0 = __ldg(wz),       q1 = __ldg(wz + 64),  q2 = __ldg(wz + 128);
        float q3 = __ldg(wz + 192), q4 = __ldg(wz + 256), q5 = __ldg(wz + 320);
        float q6 = __ldg(wz + 384), q7 = __ldg(wz + 448), q8 = __ldg(wz + 512);
        float vn2 = vd0*vd0 + vd1*vd1 + vd2*vd2;
        float s2  = sd * sd;
        float sout = q0*sd + q1*s2 + q2*vn2 + q3*s2*sd + q4*sd*vn2;
        float gv   = q5 + q6*sd + q7*s2 + q8*vn2;
        so[g] = sout;
        vo[g] = gv*vd0; vo[64 + g] = gv*vd1; vo[128 + g] = gv*vd2;
        asm volatile("bar.sync %0, 64;" :: "r"(bar) : "memory");

        float sp = 0.f, vp0 = 0.f, vp1 = 0.f, vp2 = 0.f;
        #pragma unroll 8
        for (int f = 0; f < 64; f++) {
            float a  = so[f];
            float a0 = vo[f], a1 = vo[64 + f], a2 = vo[128 + f];
            float w1 = sWps[f*64 + g], w2 = sWpv[f*64 + g];
            sp += a * w1; vp0 += a0 * w2; vp1 += a1 * w2; vp2 += a2 * w2;
        }
        sp  = sp  * 0.125f + g_skip_s[n*64 + g];
        vp0 = vp0 * 0.125f + g_skip_v[0*NF + n*64 + g];
        vp1 = vp1 * 0.125f + g_skip_v[1*NF + n*64 + g];
        vp2 = vp2 * 0.125f + g_skip_v[2*NF + n*64 + g];

        float* mrow = out + NN + (size_t)n * 256;
        mrow[g] = sp;
        mrow[64 + g*3]     = vp0;
        mrow[64 + g*3 + 1] = vp1;
        mrow[64 + g*3 + 2] = vp2;

        red[g] = sp * __ldg(Wout + g);
        asm volatile("bar.sync %0, 64;" :: "r"(bar) : "memory");
        if (g == 0) {
            float t2 = 0.f;
            #pragma unroll
            for (int i = 0; i < 64; i++) t2 += red[i];
            out[n] = t2 * 0.125f;
        }
        asm volatile("bar.sync %0, 64;" :: "r"(bar) : "memory");
    }
}

// ---------------- launch: chunked mlp -> tp pipeline on two streams ----------------
extern "C" void kernel_launch(void* const* d_in, const int* in_sizes, int n_in,
                              void* d_out, int out_size) {
    const float* vectors    = (const float*)d_in[0];
    const float* node_feats = (const float*)d_in[1];
    const float* re         = (const float*)d_in[2];
    const float* Wss        = (const float*)d_in[3];
    const float* Wsv        = (const float*)d_in[4];
    const float* Wus        = (const float*)d_in[5];
    const float* Wuv        = (const float*)d_in[6];
    const float* W1         = (const float*)d_in[7];
    const float* W2         = (const float*)d_in[8];
    const float* W3         = (const float*)d_in[9];
    const float* W4         = (const float*)d_in[10];
    const float* Wds        = (const float*)d_in[11];
    const float* Wdv        = (const float*)d_in[12];
    const float* Wsc        = (const float*)d_in[13];
    const float* Wps        = (const float*)d_in[14];
    const float* Wpv        = (const float*)d_in[15];
    const float* Wout       = (const float*)d_in[16];
    const int*   species    = (const int*)d_in[17];
    const int*   senders    = (const int*)d_in[18];
    const int*   receivers  = (const int*)d_in[19];
    float* out = (float*)d_out;

    const int MLP_SMEM  = MLP_SMEM_FLOATS * 4;    // 195584 B
    const int POST_SMEM = POST_SMEM_FLOATS * 4;   // 83968 B
    cudaFuncSetAttribute(mlp_kernel, cudaFuncAttributeMaxDynamicSharedMemorySize, MLP_SMEM);
    cudaFuncSetAttribute(node_post,  cudaFuncAttributeMaxDynamicSharedMemorySize, POST_SMEM);

    zero_agg<<<2048, 256>>>();
    node_pre<<<444, 512>>>(node_feats, Wss, Wsv, Wus, Wuv, species);

    // chunked pipeline: 7 chunks (6 x 148 blocks + 1 x 136 blocks), tp on side stream
    cudaStream_t s2;
    cudaStreamCreateWithFlags(&s2, cudaStreamNonBlocking);
    const int NCHUNK = 7;
    cudaEvent_t ev[NCHUNK], done;
    for (int c = 0; c < NCHUNK; c++) cudaEventCreateWithFlags(&ev[c], cudaEventDisableTiming);
    cudaEventCreateWithFlags(&done, cudaEventDisableTiming);

    int TOTAL_BLOCKS = EE / 256;        // 1024
    int block_base = 0;
    for (int c = 0; c < NCHUNK; c++) {
        int blocks_c = (c < NCHUNK - 1) ? 148 : (TOTAL_BLOCKS - 148*(NCHUNK-1));   // 148.. / 136
        mlp_kernel<<<blocks_c, 512, MLP_SMEM>>>(re, W1, W2, W3, W4, block_base);
        cudaEventRecord(ev[c], 0);
        cudaStreamWaitEvent(s2, ev[c], 0);
        tp_scatter<<<blocks_c * 64, 256, 0, s2>>>(vectors, senders, receivers, block_base * 256);
        block_base += blocks_c;
    }
    cudaEventRecord(done, s2);
    cudaStreamWaitEvent(0, done, 0);

    node_post<<<296, 512, POST_SMEM>>>(Wds, Wdv, Wsc, Wps, Wpv, Wout, species, out);

    for (int c = 0; c < NCHUNK; c++) cudaEventDestroy(ev[c]);
    cudaEventDestroy(done);
    cudaStreamDestroy(s2);
}

// round 12
// speedup vs baseline: 1.0619x; 1.0328x over previous
#include <cuda_runtime.h>
#include <math.h>

#define NN 32768
#define EE 262144
#define FF 64
#define PSC 9
#define NF (NN*FF)
#define HT 260   // transposed h row stride (floats): row k holds 256 edge values + pad

typedef unsigned long long u64;

// ---------------- device scratch ----------------
__device__ float g_skip_s[NF];
__device__ float g_skip_v[3*NF];
__device__ float g_sup[NF];
__device__ float g_vup[3*NF];
__device__ float g_agg_s[NF];
__device__ float g_agg_v[3*NF];
__device__ float g_w[(size_t)EE*320];   // per-edge TP path weights [E,5,64]

// ---------------- f32x2 packed-math helpers ----------------
__device__ __forceinline__ u64 pack2(float x) {
    u64 r; asm("mov.b64 %0, {%1, %1};" : "=l"(r) : "f"(x)); return r;
}
__device__ __forceinline__ u64 fma2(u64 a, u64 b, u64 c) {
    u64 d; asm("fma.rn.f32x2 %0, %1, %2, %3;" : "=l"(d) : "l"(a), "l"(b), "l"(c)); return d;
}
__device__ __forceinline__ float2 unpk(u64 a) {
    float2 f; asm("mov.b64 {%0, %1}, %2;" : "=f"(f.x), "=f"(f.y) : "l"(a)); return f;
}
__device__ __forceinline__ float silu(float x) { return x / (1.f + __expf(-x)); }

// ---------------- kernel A: per-species skip linear + linear_up + fused agg zeroing ----------------
__global__ void __launch_bounds__(512)
node_pre(const float* __restrict__ nf,
         const float* __restrict__ Wss,
         const float* __restrict__ Wsv,
         const float* __restrict__ Wus,
         const float* __restrict__ Wuv,
         const int*   __restrict__ species) {
    __shared__ float sWus[FF*FF], sWuv[FF*FF];
    __shared__ float s_sh[8][FF];
    __shared__ float v_sh[8][3*FF];
    int tid = threadIdx.x;

    // fused zeroing of aggregation buffers (consumed by tp_scatter, 2 launches later)
    {
        int t = blockIdx.x * 512 + tid;
        int stride = gridDim.x * 512;
        float4 z4 = make_float4(0.f, 0.f, 0.f, 0.f);
        float4* a = (float4*)g_agg_s;
        float4* v = (float4*)g_agg_v;
        for (int i = t; i < NF/4; i += stride) a[i] = z4;
        for (int i = t; i < 3*NF/4; i += stride) v[i] = z4;
    }

    for (int i = tid; i < FF*FF; i += 512) { sWus[i] = Wus[i]; sWuv[i] = Wuv[i]; }
    __syncthreads();
    int g = tid & 63, grp = tid >> 6;
    int bar = grp + 1;
    int group_id = blockIdx.x * 8 + grp;
    int totalGroups = gridDim.x * 8;
    for (int n = group_id; n < NN; n += totalGroups) {
        const float* row = nf + (size_t)n * 256;
        s_sh[grp][g]        = row[g];
        v_sh[grp][g]        = row[64 + g];
        v_sh[grp][64 + g]   = row[128 + g];
        v_sh[grp][128 + g]  = row[192 + g];
        asm volatile("bar.sync %0, 64;" :: "r"(bar) : "memory");
        int z = species[n];
        const float* wssz = Wss + z * 4096;
        const float* wsvz = Wsv + z * 4096;
        float ks = 0.f, kv0 = 0.f, kv1 = 0.f, kv2 = 0.f;
        float us = 0.f, uv0 = 0.f, uv1 = 0.f, uv2 = 0.f;
        #pragma unroll 8
        for (int f = 0; f < FF; f++) {
            float sv = s_sh[grp][f];
            float a0 = v_sh[grp][f*3], a1 = v_sh[grp][f*3+1], a2 = v_sh[grp][f*3+2];
            float w1 = __ldg(wssz + f*64 + g);
            float w2 = __ldg(wsvz + f*64 + g);
            float w3 = sWus[f*64 + g];
            float w4 = sWuv[f*64 + g];
            ks  += sv * w1; kv0 += a0 * w2; kv1 += a1 * w2; kv2 += a2 * w2;
            us  += sv * w3; uv0 += a0 * w4; uv1 += a1 * w4; uv2 += a2 * w4;
        }
        const float invZ = 0.039528471f;
        const float inv  = 0.125f;
        g_skip_s[n*64 + g]          = ks  * invZ;
        g_skip_v[0*NF + n*64 + g]   = kv0 * invZ;
        g_skip_v[1*NF + n*64 + g]   = kv1 * invZ;
        g_skip_v[2*NF + n*64 + g]   = kv2 * invZ;
        g_sup[n*64 + g]             = us  * inv;
        g_vup[0*NF + n*64 + g]      = uv0 * inv;
        g_vup[1*NF + n*64 + g]      = uv1 * inv;
        g_vup[2*NF + n*64 + g]      = uv2 * inv;
        asm volatile("bar.sync %0, 64;" :: "r"(bar) : "memory");
    }
}

// ---------------- kernel B1: radial MLP, transposed h (h_t[k][edge]) ----------------
// smem floats: W1 512 | W2 4096 | W3 4096 | W4 20480 | RE 2048 | h_t 64*HT (16640)
#define MLP_SMEM_FLOATS (512 + 4096 + 4096 + 20480 + 2048 + 64*HT)

__device__ __forceinline__ void zacc(u64 acc[4][4]) {
    #pragma unroll
    for (int gp = 0; gp < 4; gp++)
        #pragma unroll
        for (int ee = 0; ee < 4; ee++) acc[gp][ee] = 0ull;
}

// one k-step: load 4 edges' h via one LDS.128 from transposed row, weights via 2 LDS.128
__device__ __forceinline__ void kstep_t(const float* __restrict__ h_t, int e0, int k,
                                        const float* __restrict__ wrow, u64 acc[4][4]) {
    float4 hv = *(const float4*)(h_t + k*HT + e0);
    u64 hp0 = pack2(hv.x), hp1 = pack2(hv.y), hp2 = pack2(hv.z), hp3 = pack2(hv.w);
    ulonglong2 wa = *(const ulonglong2*)(wrow);
    ulonglong2 wb = *(const ulonglong2*)(wrow + 4);
    acc[0][0] = fma2(hp0, wa.x, acc[0][0]); acc[0][1] = fma2(hp1, wa.x, acc[0][1]);
    acc[0][2] = fma2(hp2, wa.x, acc[0][2]); acc[0][3] = fma2(hp3, wa.x, acc[0][3]);
    acc[1][0] = fma2(hp0, wa.y, acc[1][0]); acc[1][1] = fma2(hp1, wa.y, acc[1][1]);
    acc[1][2] = fma2(hp2, wa.y, acc[1][2]); acc[1][3] = fma2(hp3, wa.y, acc[1][3]);
    acc[2][0] = fma2(hp0, wb.x, acc[2][0]); acc[2][1] = fma2(hp1, wb.x, acc[2][1]);
    acc[2][2] = fma2(hp2, wb.x, acc[2][2]); acc[2][3] = fma2(hp3, wb.x, acc[2][3]);
    acc[3][0] = fma2(hp0, wb.y, acc[3][0]); acc[3][1] = fma2(hp1, wb.y, acc[3][1]);
    acc[3][2] = fma2(hp2, wb.y, acc[3][2]); acc[3][3] = fma2(hp3, wb.y, acc[3][3]);
}

// write transposed: channel rows, edge columns (register transpose, 8 float4 stores)
__device__ __forceinline__ void write_silu_t(u64 acc[4][4], float* h_t, int e0, int g0, float scale) {
    #pragma unroll
    for (int gp = 0; gp < 4; gp++) {
        float2 t0 = unpk(acc[gp][0]), t1 = unpk(acc[gp][1]);
        float2 t2 = unpk(acc[gp][2]), t3 = unpk(acc[gp][3]);
        int c = g0 + gp*2;
        *(float4*)(h_t + c*HT + e0) =
            make_float4(silu(t0.x*scale), silu(t1.x*scale), silu(t2.x*scale), silu(t3.x*scale));
        *(float4*)(h_t + (c+1)*HT + e0) =
            make_float4(silu(t0.y*scale), silu(t1.y*scale), silu(t2.y*scale), silu(t3.y*scale));
    }
}

__global__ void __launch_bounds__(512)
mlp_kernel(const float* __restrict__ re,
           const float* __restrict__ W1,
           const float* __restrict__ W2,
           const float* __restrict__ W3,
           const float* __restrict__ W4) {
    extern __shared__ float sm[];
    float* sW1 = sm;
    float* sW2 = sW1 + 512;
    float* sW3 = sW2 + 4096;
    float* sW4 = sW3 + 4096;
    float* sRE = sW4 + 20480;
    float* h_t = sRE + 2048;
    int tid = threadIdx.x;
    for (int i = tid; i < 512;   i += 512) sW1[i] = W1[i];
    for (int i = tid; i < 4096;  i += 512) { sW2[i] = W2[i]; sW3[i] = W3[i]; }
    for (int i = tid; i < 20480; i += 512) sW4[i] = W4[i];

    int e_base = blockIdx.x * 256;
    for (int i = tid; i < 2048; i += 512) sRE[i] = re[(size_t)e_base*8 + i];
    __syncthreads();

    int cj = tid & 7, ei = tid >> 3;
    int g0 = cj * 8, e0 = ei * 4;

    u64 acc[4][4];

    // layer 1: K=8 (reads sRE, writes h_t)
    zacc(acc);
    #pragma unroll
    for (int k = 0; k < 8; k++) {
        u64 hp[4];
        #pragma unroll
        for (int ee = 0; ee < 4; ee++) hp[ee] = pack2(sRE[(e0+ee)*8 + k]);
        ulonglong2 wa = *(const ulonglong2*)(sW1 + k*64 + g0);
        ulonglong2 wb = *(const ulonglong2*)(sW1 + k*64 + g0 + 4);
        #pragma unroll
        for (int ee = 0; ee < 4; ee++) {
            acc[0][ee] = fma2(hp[ee], wa.x, acc[0][ee]);
            acc[1][ee] = fma2(hp[ee], wa.y, acc[1][ee]);
            acc[2][ee] = fma2(hp[ee], wb.x, acc[2][ee]);
            acc[3][ee] = fma2(hp[ee], wb.y, acc[3][ee]);
        }
    }
    write_silu_t(acc, h_t, e0, g0, 0.35355339f);   // 1/sqrt(8)
    __syncthreads();

    // layer 2: in-place (compute all reads -> barrier -> write -> barrier)
    zacc(acc);
    #pragma unroll 4
    for (int k = 0; k < 64; k++) kstep_t(h_t, e0, k, sW2 + k*64 + g0, acc);
    __syncthreads();
    write_silu_t(acc, h_t, e0, g0, 0.125f);
    __syncthreads();

    // layer 3: in-place
    zacc(acc);
    #pragma unroll 4
    for (int k = 0; k < 64; k++) kstep_t(h_t, e0, k, sW3 + k*64 + g0, acc);
    __syncthreads();
    write_silu_t(acc, h_t, e0, g0, 0.125f);
    __syncthreads();

    // layer 4: 5 path slices of W4, write g_w
    #pragma unroll
    for (int p = 0; p < 5; p++) {
        zacc(acc);
        #pragma unroll 4
        for (int k = 0; k < 64; k++) kstep_t(h_t, e0, k, sW4 + k*320 + p*64 + g0, acc);
        #pragma unroll
        for (int ee = 0; ee < 4; ee++) {
            float2 a = unpk(acc[0][ee]), b = unpk(acc[1][ee]);
            float2 c = unpk(acc[2][ee]), d = unpk(acc[3][ee]);
            float* dst = g_w + (size_t)(e_base + e0 + ee)*320 + p*64 + g0;
            *(float4*)dst       = make_float4(a.x*0.125f, a.y*0.125f, b.x*0.125f, b.y*0.125f);
            *(float4*)(dst + 4) = make_float4(c.x*0.125f, c.y*0.125f, d.x*0.125f, d.y*0.125f);
        }
    }
}

// ---------------- kernel B2: tensor product + scatter (R8 exact) ----------------
__global__ void tp_scatter(const float* __restrict__ vectors,
                           const int* __restrict__ senders,
                           const int* __restrict__ receivers) {
    int t = blockIdx.x * 256 + threadIdx.x;
    int e = t >> 6, g = t & 63;
    float vx = __ldg(vectors + e*3), vy = __ldg(vectors + e*3 + 1), vz = __ldg(vectors + e*3 + 2);
    float rn = 1.f / (sqrtf(vx*vx + vy*vy + vz*vz) + 1e-9f);
    float y0 = vx * rn, y1 = vy * rn, y2 = vz * rn;

    const float* wrow = g_w + (size_t)e*320 + g;
    float w0  = wrow[0];
    float w1a = wrow[64];
    float w2a = wrow[128];
    float w3a = wrow[192];
    float w4a = wrow[256];

    int sn = __ldg(senders + e), rc = __ldg(receivers + e);
    float ss = g_sup[sn*64 + g];
    float b0 = g_vup[0*NF + sn*64 + g];
    float b1 = g_vup[1*NF + sn*64 + g];
    float b2 = g_vup[2*NF + sn*64 + g];
    float dot = b0*y0 + b1*y1 + b2*y2;
    float c0 = b1*y2 - b2*y1;
    float c1 = b2*y0 - b0*y2;
    float c2 = b0*y1 - b1*y0;
    const float is2 = 0.70710678f;
    float ms  = (w0*ss + w3a*dot) * 0.25f;
    float mv0 = (w1a*y0 + w2a*b0 + w4a*c0*is2) * 0.25f;
    float mv1 = (w1a*y1 + w2a*b1 + w4a*c1*is2) * 0.25f;
    float mv2 = (w1a*y2 + w2a*b2 + w4a*c2*is2) * 0.25f;
    atomicAdd(&g_agg_s[rc*64 + g], ms);
    atomicAdd(&g_agg_v[0*NF + rc*64 + g], mv0);
    atomicAdd(&g_agg_v[1*NF + rc*64 + g], mv1);
    atomicAdd(&g_agg_v[2*NF + rc*64 + g], mv2);
}

// ---------------- kernel C: node_post (R8 exact, 512 thr) ----------------
#define POST_SMEM_FLOATS (4*4096 + 8*576)
__global__ void __launch_bounds__(512)
node_post(const float* __restrict__ Wds,
          const float* __restrict__ Wdv,
          const float* __restrict__ Wsc,
          const float* __restrict__ Wps,
          const float* __restrict__ Wpv,
          const float* __restrict__ Wout,
          const int*   __restrict__ species,
          float* __restrict__ out) {
    extern __shared__ float sm[];
    float* sWds = sm;
    float* sWdv = sm + 4096;
    float* sWps = sm + 8192;
    float* sWpv = sm + 12288;
    float* buf  = sm + 16384;
    int tid = threadIdx.x;
    for (int i = tid; i < 4096; i += 512) {
        sWds[i] = Wds[i]; sWdv[i] = Wdv[i]; sWps[i] = Wps[i]; sWpv[i] = Wpv[i];
    }
    __syncthreads();
    int g = tid & 63, grp = tid >> 6, bar = grp + 1;
    float* ags = buf + grp * 576;
    float* agv = ags + 64;
    float* so  = agv + 192;
    float* vo  = so + 64;
    float* red = vo + 192;
    int group_id = blockIdx.x * 8 + grp;
    int totalGroups = gridDim.x * 8;
    for (int n = group_id; n < NN; n += totalGroups) {
        ags[g]       = g_agg_s[n*64 + g];
        agv[g]       = g_agg_v[0*NF + n*64 + g];
        agv[64 + g]  = g_agg_v[1*NF + n*64 + g];
        agv[128 + g] = g_agg_v[2*NF + n*64 + g];
        asm volatile("bar.sync %0, 64;" :: "r"(bar) : "memory");

        float sd = 0.f, vd0 = 0.f, vd1 = 0.f, vd2 = 0.f;
        #pragma unroll 8
        for (int f = 0; f < 64; f++) {
            float a  = ags[f];
            float a0 = agv[f], a1 = agv[64 + f], a2 = agv[128 + f];
            float w1 = sWds[f*64 + g], w2 = sWdv[f*64 + g];
            sd += a * w1; vd0 += a0 * w2; vd1 += a1 * w2; vd2 += a2 * w2;
        }
        sd *= 0.125f; vd0 *= 0.125f; vd1 *= 0.125f; vd2 *= 0.125f;

        int z = species[n];
        const float* wz = Wsc + z * (PSC*64) + g;
        float q0 = __ldg(wz),       q1 = __ldg(wz + 64),  q2 = __ldg(wz + 128);
        float q3 = __ldg(wz + 192), q4 = __ldg(wz + 256), q5 = __ldg(wz + 320);
        float q6 = __ldg(wz + 384), q7 = __ldg(wz + 448), q8 = __ldg(wz + 512);
        float vn2 = vd0*vd0 + vd1*vd1 + vd2*vd2;
        float s2  = sd * sd;
        float sout = q0*sd + q1*s2 + q2*vn2 + q3*s2*sd + q4*sd*vn2;
        float gv   = q5 + q6*sd + q7*s2 + q8*vn2;
        so[g] = sout;
        vo[g] = gv*vd0; vo[64 + g] = gv*vd1; vo[128 + g] = gv*vd2;
        asm volatile("bar.sync %0, 64;" :: "r"(bar) : "memory");

        float sp = 0.f, vp0 = 0.f, vp1 = 0.f, vp2 = 0.f;
        #pragma unroll 8
        for (int f = 0; f < 64; f++) {
            float a  = so[f];
            float a0 = vo[f], a1 = vo[64 + f], a2 = vo[128 + f];
            float w1 = sWps[f*64 + g], w2 = sWpv[f*64 + g];
            sp += a * w1; vp0 += a0 * w2; vp1 += a1 * w2; vp2 += a2 * w2;
        }
        sp  = sp  * 0.125f + g_skip_s[n*64 + g];
        vp0 = vp0 * 0.125f + g_skip_v[0*NF + n*64 + g];
        vp1 = vp1 * 0.125f + g_skip_v[1*NF + n*64 + g];
        vp2 = vp2 * 0.125f + g_skip_v[2*NF + n*64 + g];

        float* mrow = out + NN + (size_t)n * 256;
        mrow[g] = sp;
        mrow[64 + g*3]     = vp0;
        mrow[64 + g*3 + 1] = vp1;
        mrow[64 + g*3 + 2] = vp2;

        red[g] = sp * __ldg(Wout + g);
        asm volatile("bar.sync %0, 64;" :: "r"(bar) : "memory");
        if (g == 0) {
            float t2 = 0.f;
            #pragma unroll
            for (int i = 0; i < 64; i++) t2 += red[i];
            out[n] = t2 * 0.125f;
        }
        asm volatile("bar.sync %0, 64;" :: "r"(bar) : "memory");
    }
}

// ---------------- launch ----------------
extern "C" void kernel_launch(void* const* d_in, const int* in_sizes, int n_in,
                              void* d_out, int out_size) {
    const float* vectors    = (const float*)d_in[0];
    const float* node_feats = (const float*)d_in[1];
    const float* re         = (const float*)d_in[2];
    const float* Wss        = (const float*)d_in[3];
    const float* Wsv        = (const float*)d_in[4];
    const float* Wus        = (const float*)d_in[5];
    const float* Wuv        = (const float*)d_in[6];
    const float* W1         = (const float*)d_in[7];
    const float* W2         = (const float*)d_in[8];
    const float* W3         = (const float*)d_in[9];
    const float* W4         = (const float*)d_in[10];
    const float* Wds        = (const float*)d_in[11];
    const float* Wdv        = (const float*)d_in[12];
    const float* Wsc        = (const float*)d_in[13];
    const float* Wps        = (const float*)d_in[14];
    const float* Wpv        = (const float*)d_in[15];
    const float* Wout       = (const float*)d_in[16];
    const int*   species    = (const int*)d_in[17];
    const int*   senders    = (const int*)d_in[18];
    const int*   receivers  = (const int*)d_in[19];
    float* out = (float*)d_out;

    const int MLP_SMEM  = MLP_SMEM_FLOATS * 4;    // 191488 B
    const int POST_SMEM = POST_SMEM_FLOATS * 4;   // 83968 B
    cudaFuncSetAttribute(mlp_kernel, cudaFuncAttributeMaxDynamicSharedMemorySize, MLP_SMEM);
    cudaFuncSetAttribute(node_post,  cudaFuncAttributeMaxDynamicSharedMemorySize, POST_SMEM);

    node_pre<<<444, 512>>>(node_feats, Wss, Wsv, Wus, Wuv, species);
    mlp_kernel<<<EE/256, 512, MLP_SMEM>>>(re, W1, W2, W3, W4);
    tp_scatter<<<EE*64/256, 256>>>(vectors, senders, receivers);
    node_post<<<296, 512, POST_SMEM>>>(Wds, Wdv, Wsc, Wps, Wpv, Wout, species, out);
}

// round 13
// speedup vs baseline: 1.1009x; 1.0368x over previous
#include <cuda_runtime.h>
#include <cuda_fp16.h>
#include <math.h>

#define NN 32768
#define EE 262144
#define FF 64
#define PSC 9
#define NF (NN*FF)
#define HS 68   // padded row stride (floats)

typedef unsigned long long u64;

// ---------------- device scratch ----------------
__device__ float g_skip_s[NF];
__device__ float g_skip_v[3*NF];
__device__ float g_sup[NF];
__device__ float g_vup[3*NF];
__device__ float g_agg_s[NF];
__device__ float g_agg_v[3*NF];
__device__ __half g_wh[(size_t)EE*320];   // per-edge TP path weights [E,5,64], fp16

// ---------------- f32x2 packed-math helpers ----------------
__device__ __forceinline__ u64 pack2(float x) {
    u64 r; asm("mov.b64 %0, {%1, %1};" : "=l"(r) : "f"(x)); return r;
}
__device__ __forceinline__ u64 fma2(u64 a, u64 b, u64 c) {
    u64 d; asm("fma.rn.f32x2 %0, %1, %2, %3;" : "=l"(d) : "l"(a), "l"(b), "l"(c)); return d;
}
__device__ __forceinline__ float2 unpk(u64 a) {
    float2 f; asm("mov.b64 {%0, %1}, %2;" : "=f"(f.x), "=f"(f.y) : "l"(a)); return f;
}
__device__ __forceinline__ float silu(float x) { return x / (1.f + __expf(-x)); }

__global__ void zero_agg() {
    int stride = gridDim.x * blockDim.x;
    int t = blockIdx.x * blockDim.x + threadIdx.x;
    for (int i = t; i < NF; i += stride) g_agg_s[i] = 0.f;
    for (int i = t; i < 3*NF; i += stride) g_agg_v[i] = 0.f;
}

// ---------------- kernel A: per-species skip linear + linear_up (R8 exact) ----------------
__global__ void __launch_bounds__(512)
node_pre(const float* __restrict__ nf,
         const float* __restrict__ Wss,
         const float* __restrict__ Wsv,
         const float* __restrict__ Wus,
         const float* __restrict__ Wuv,
         const int*   __restrict__ species) {
    __shared__ float sWus[FF*FF], sWuv[FF*FF];
    __shared__ float s_sh[8][FF];
    __shared__ float v_sh[8][3*FF];
    int tid = threadIdx.x;
    for (int i = tid; i < FF*FF; i += 512) { sWus[i] = Wus[i]; sWuv[i] = Wuv[i]; }
    __syncthreads();
    int g = tid & 63, grp = tid >> 6;
    int bar = grp + 1;
    int group_id = blockIdx.x * 8 + grp;
    int totalGroups = gridDim.x * 8;
    for (int n = group_id; n < NN; n += totalGroups) {
        const float* row = nf + (size_t)n * 256;
        s_sh[grp][g]        = row[g];
        v_sh[grp][g]        = row[64 + g];
        v_sh[grp][64 + g]   = row[128 + g];
        v_sh[grp][128 + g]  = row[192 + g];
        asm volatile("bar.sync %0, 64;" :: "r"(bar) : "memory");
        int z = species[n];
        const float* wssz = Wss + z * 4096;
        const float* wsvz = Wsv + z * 4096;
        float ks = 0.f, kv0 = 0.f, kv1 = 0.f, kv2 = 0.f;
        float us = 0.f, uv0 = 0.f, uv1 = 0.f, uv2 = 0.f;
        #pragma unroll 8
        for (int f = 0; f < FF; f++) {
            float sv = s_sh[grp][f];
            float a0 = v_sh[grp][f*3], a1 = v_sh[grp][f*3+1], a2 = v_sh[grp][f*3+2];
            float w1 = __ldg(wssz + f*64 + g);
            float w2 = __ldg(wsvz + f*64 + g);
            float w3 = sWus[f*64 + g];
            float w4 = sWuv[f*64 + g];
            ks  += sv * w1; kv0 += a0 * w2; kv1 += a1 * w2; kv2 += a2 * w2;
            us  += sv * w3; uv0 += a0 * w4; uv1 += a1 * w4; uv2 += a2 * w4;
        }
        const float invZ = 0.039528471f;
        const float inv  = 0.125f;
        g_skip_s[n*64 + g]          = ks  * invZ;
        g_skip_v[0*NF + n*64 + g]   = kv0 * invZ;
        g_skip_v[1*NF + n*64 + g]   = kv1 * invZ;
        g_skip_v[2*NF + n*64 + g]   = kv2 * invZ;
        g_sup[n*64 + g]             = us  * inv;
        g_vup[0*NF + n*64 + g]      = uv0 * inv;
        g_vup[1*NF + n*64 + g]      = uv1 * inv;
        g_vup[2*NF + n*64 + g]      = uv2 * inv;
        asm volatile("bar.sync %0, 64;" :: "r"(bar) : "memory");
    }
}

// ---------------- kernel B1: radial MLP (R5 core), fp16 g_w epilogue ----------------
#define MLP_SMEM_FLOATS (512 + 4096 + 4096 + 20480 + 2048 + 256*HS)

__device__ __forceinline__ void kstep(const float* __restrict__ hin, int e0, int k,
                                      const float* __restrict__ wrow, u64 acc[4][4]) {
    u64 hp[4];
    #pragma unroll
    for (int ee = 0; ee < 4; ee++) hp[ee] = pack2(hin[(e0+ee)*HS + k]);
    ulonglong2 wa = *(const ulonglong2*)(wrow);
    ulonglong2 wb = *(const ulonglong2*)(wrow + 4);
    #pragma unroll
    for (int ee = 0; ee < 4; ee++) {
        acc[0][ee] = fma2(hp[ee], wa.x, acc[0][ee]);
        acc[1][ee] = fma2(hp[ee], wa.y, acc[1][ee]);
        acc[2][ee] = fma2(hp[ee], wb.x, acc[2][ee]);
        acc[3][ee] = fma2(hp[ee], wb.y, acc[3][ee]);
    }
}

__device__ __forceinline__ void zacc(u64 acc[4][4]) {
    #pragma unroll
    for (int gp = 0; gp < 4; gp++)
        #pragma unroll
        for (int ee = 0; ee < 4; ee++) acc[gp][ee] = 0ull;
}

__device__ __forceinline__ void write_silu(u64 acc[4][4], float* h, int e0, int g0, float scale) {
    #pragma unroll
    for (int ee = 0; ee < 4; ee++) {
        float2 a = unpk(acc[0][ee]), b = unpk(acc[1][ee]);
        float2 c = unpk(acc[2][ee]), d = unpk(acc[3][ee]);
        float4 lo = make_float4(silu(a.x*scale), silu(a.y*scale), silu(b.x*scale), silu(b.y*scale));
        float4 hi = make_float4(silu(c.x*scale), silu(c.y*scale), silu(d.x*scale), silu(d.y*scale));
        *(float4*)(h + (e0+ee)*HS + g0)     = lo;
        *(float4*)(h + (e0+ee)*HS + g0 + 4) = hi;
    }
}

__global__ void __launch_bounds__(512)
mlp_kernel(const float* __restrict__ re,
           const float* __restrict__ W1,
           const float* __restrict__ W2,
           const float* __restrict__ W3,
           const float* __restrict__ W4) {
    extern __shared__ float sm[];
    float* sW1 = sm;
    float* sW2 = sW1 + 512;
    float* sW3 = sW2 + 4096;
    float* sW4 = sW3 + 4096;
    float* sRE = sW4 + 20480;
    float* h   = sRE + 2048;
    int tid = threadIdx.x;
    for (int i = tid; i < 512;   i += 512) sW1[i] = W1[i];
    for (int i = tid; i < 4096;  i += 512) { sW2[i] = W2[i]; sW3[i] = W3[i]; }
    for (int i = tid; i < 20480; i += 512) sW4[i] = W4[i];

    int e_base = blockIdx.x * 256;
    for (int i = tid; i < 2048; i += 512) sRE[i] = re[(size_t)e_base*8 + i];
    __syncthreads();

    int cj = tid & 7, ei = tid >> 3;
    int g0 = cj * 8, e0 = ei * 4;

    u64 acc[4][4];

    zacc(acc);
    #pragma unroll
    for (int k = 0; k < 8; k++) {
        u64 hp[4];
        #pragma unroll
        for (int ee = 0; ee < 4; ee++) hp[ee] = pack2(sRE[(e0+ee)*8 + k]);
        ulonglong2 wa = *(const ulonglong2*)(sW1 + k*64 + g0);
        ulonglong2 wb = *(const ulonglong2*)(sW1 + k*64 + g0 + 4);
        #pragma unroll
        for (int ee = 0; ee < 4; ee++) {
            acc[0][ee] = fma2(hp[ee], wa.x, acc[0][ee]);
            acc[1][ee] = fma2(hp[ee], wa.y, acc[1][ee]);
            acc[2][ee] = fma2(hp[ee], wb.x, acc[2][ee]);
            acc[3][ee] = fma2(hp[ee], wb.y, acc[3][ee]);
        }
    }
    write_silu(acc, h, e0, g0, 0.35355339f);
    __syncthreads();

    zacc(acc);
    #pragma unroll 4
    for (int k = 0; k < 64; k++) kstep(h, e0, k, sW2 + k*64 + g0, acc);
    __syncthreads();
    write_silu(acc, h, e0, g0, 0.125f);
    __syncthreads();

    zacc(acc);
    #pragma unroll 4
    for (int k = 0; k < 64; k++) kstep(h, e0, k, sW3 + k*64 + g0, acc);
    __syncthreads();
    write_silu(acc, h, e0, g0, 0.125f);
    __syncthreads();

    // layer 4: 5 path slices of W4, write g_wh (fp16)
    #pragma unroll
    for (int p = 0; p < 5; p++) {
        zacc(acc);
        #pragma unroll 4
        for (int k = 0; k < 64; k++) kstep(h, e0, k, sW4 + k*320 + p*64 + g0, acc);
        #pragma unroll
        for (int ee = 0; ee < 4; ee++) {
            float2 a = unpk(acc[0][ee]), b = unpk(acc[1][ee]);
            float2 c = unpk(acc[2][ee]), d = unpk(acc[3][ee]);
            __half2 h0 = __floats2half2_rn(a.x*0.125f, a.y*0.125f);
            __half2 h1 = __floats2half2_rn(b.x*0.125f, b.y*0.125f);
            __half2 h2 = __floats2half2_rn(c.x*0.125f, c.y*0.125f);
            __half2 h3 = __floats2half2_rn(d.x*0.125f, d.y*0.125f);
            __half2* dst = (__half2*)(g_wh + (size_t)(e_base + e0 + ee)*320 + p*64 + g0);
            uint4 pk;
            pk.x = *(unsigned*)&h0; pk.y = *(unsigned*)&h1;
            pk.z = *(unsigned*)&h2; pk.w = *(unsigned*)&h3;
            *(uint4*)dst = pk;   // 16B store: 8 channels as fp16
        }
    }
}

// ---------------- kernel B2: tensor product + scatter (fp16 w read) ----------------
__global__ void tp_scatter(const float* __restrict__ vectors,
                           const int* __restrict__ senders,
                           const int* __restrict__ receivers) {
    int t = blockIdx.x * 256 + threadIdx.x;
    int e = t >> 6, g = t & 63;
    float vx = __ldg(vectors + e*3), vy = __ldg(vectors + e*3 + 1), vz = __ldg(vectors + e*3 + 2);
    float rn = 1.f / (sqrtf(vx*vx + vy*vy + vz*vz) + 1e-9f);
    float y0 = vx * rn, y1 = vy * rn, y2 = vz * rn;

    const __half* wrow = g_wh + (size_t)e*320 + g;
    float w0  = __half2float(wrow[0]);
    float w1a = __half2float(wrow[64]);
    float w2a = __half2float(wrow[128]);
    float w3a = __half2float(wrow[192]);
    float w4a = __half2float(wrow[256]);

    int sn = __ldg(senders + e), rc = __ldg(receivers + e);
    float ss = g_sup[sn*64 + g];
    float b0 = g_vup[0*NF + sn*64 + g];
    float b1 = g_vup[1*NF + sn*64 + g];
    float b2 = g_vup[2*NF + sn*64 + g];
    float dot = b0*y0 + b1*y1 + b2*y2;
    float c0 = b1*y2 - b2*y1;
    float c1 = b2*y0 - b0*y2;
    float c2 = b0*y1 - b1*y0;
    const float is2 = 0.70710678f;
    float ms  = (w0*ss + w3a*dot) * 0.25f;
    float mv0 = (w1a*y0 + w2a*b0 + w4a*c0*is2) * 0.25f;
    float mv1 = (w1a*y1 + w2a*b1 + w4a*c1*is2) * 0.25f;
    float mv2 = (w1a*y2 + w2a*b2 + w4a*c2*is2) * 0.25f;
    atomicAdd(&g_agg_s[rc*64 + g], ms);
    atomicAdd(&g_agg_v[0*NF + rc*64 + g], mv0);
    atomicAdd(&g_agg_v[1*NF + rc*64 + g], mv1);
    atomicAdd(&g_agg_v[2*NF + rc*64 + g], mv2);
}

// ---------------- kernel C: node_post (R8 exact, 512 thr) ----------------
#define POST_SMEM_FLOATS (4*4096 + 8*576)
__global__ void __launch_bounds__(512)
node_post(const float* __restrict__ Wds,
          const float* __restrict__ Wdv,
          const float* __restrict__ Wsc,
          const float* __restrict__ Wps,
          const float* __restrict__ Wpv,
          const float* __restrict__ Wout,
          const int*   __restrict__ species,
          float* __restrict__ out) {
    extern __shared__ float sm[];
    float* sWds = sm;
    float* sWdv = sm + 4096;
    float* sWps = sm + 8192;
    float* sWpv = sm + 12288;
    float* buf  = sm + 16384;
    int tid = threadIdx.x;
    for (int i = tid; i < 4096; i += 512) {
        sWds[i] = Wds[i]; sWdv[i] = Wdv[i]; sWps[i] = Wps[i]; sWpv[i] = Wpv[i];
    }
    __syncthreads();
    int g = tid & 63, grp = tid >> 6, bar = grp + 1;
    float* ags = buf + grp * 576;
    float* agv = ags + 64;
    float* so  = agv + 192;
    float* vo  = so + 64;
    float* red = vo + 192;
    int group_id = blockIdx.x * 8 + grp;
    int totalGroups = gridDim.x * 8;
    for (int n = group_id; n < NN; n += totalGroups) {
        ags[g]       = g_agg_s[n*64 + g];
        agv[g]       = g_agg_v[0*NF + n*64 + g];
        agv[64 + g]  = g_agg_v[1*NF + n*64 + g];
        agv[128 + g] = g_agg_v[2*NF + n*64 + g];
        asm volatile("bar.sync %0, 64;" :: "r"(bar) : "memory");

        float sd = 0.f, vd0 = 0.f, vd1 = 0.f, vd2 = 0.f;
        #pragma unroll 8
        for (int f = 0; f < 64; f++) {
            float a  = ags[f];
            float a0 = agv[f], a1 = agv[64 + f], a2 = agv[128 + f];
            float w1 = sWds[f*64 + g], w2 = sWdv[f*64 + g];
            sd += a * w1; vd0 += a0 * w2; vd1 += a1 * w2; vd2 += a2 * w2;
        }
        sd *= 0.125f; vd0 *= 0.125f; vd1 *= 0.125f; vd2 *= 0.125f;

        int z = species[n];
        const float* wz = Wsc + z * (PSC*64) + g;
        float q0 = __ldg(wz),       q1 = __ldg(wz + 64),  q2 = __ldg(wz + 128);
        float q3 = __ldg(wz + 192), q4 = __ldg(wz + 256), q5 = __ldg(wz + 320);
        float q6 = __ldg(wz + 384), q7 = __ldg(wz + 448), q8 = __ldg(wz + 512);
        float vn2 = vd0*vd0 + vd1*vd1 + vd2*vd2;
        float s2  = sd * sd;
        float sout = q0*sd + q1*s2 + q2*vn2 + q3*s2*sd + q4*sd*vn2;
        float gv   = q5 + q6*sd + q7*s2 + q8*vn2;
        so[g] = sout;
        vo[g] = gv*vd0; vo[64 + g] = gv*vd1; vo[128 + g] = gv*vd2;
        asm volatile("bar.sync %0, 64;" :: "r"(bar) : "memory");

        float sp = 0.f, vp0 = 0.f, vp1 = 0.f, vp2 = 0.f;
        #pragma unroll 8
        for (int f = 0; f < 64; f++) {
            float a  = so[f];
            float a0 = vo[f], a1 = vo[64 + f], a2 = vo[128 + f];
            float w1 = sWps[f*64 + g], w2 = sWpv[f*64 + g];
            sp += a * w1; vp0 += a0 * w2; vp1 += a1 * w2; vp2 += a2 * w2;
        }
        sp  = sp  * 0.125f + g_skip_s[n*64 + g];
        vp0 = vp0 * 0.125f + g_skip_v[0*NF + n*64 + g];
        vp1 = vp1 * 0.125f + g_skip_v[1*NF + n*64 + g];
        vp2 = vp2 * 0.125f + g_skip_v[2*NF + n*64 + g];

        float* mrow = out + NN + (size_t)n * 256;
        mrow[g] = sp;
        mrow[64 + g*3]     = vp0;
        mrow[64 + g*3 + 1] = vp1;
        mrow[64 + g*3 + 2] = vp2;

        red[g] = sp * __ldg(Wout + g);
        asm volatile("bar.sync %0, 64;" :: "r"(bar) : "memory");
        if (g == 0) {
            float t2 = 0.f;
            #pragma unroll
            for (int i = 0; i < 64; i++) t2 += red[i];
            out[n] = t2 * 0.125f;
        }
        asm volatile("bar.sync %0, 64;" :: "r"(bar) : "memory");
    }
}

// ---------------- launch ----------------
extern "C" void kernel_launch(void* const* d_in, const int* in_sizes, int n_in,
                              void* d_out, int out_size) {
    const float* vectors    = (const float*)d_in[0];
    const float* node_feats = (const float*)d_in[1];
    const float* re         = (const float*)d_in[2];
    const float* Wss        = (const float*)d_in[3];
    const float* Wsv        = (const float*)d_in[4];
    const float* Wus        = (const float*)d_in[5];
    const float* Wuv        = (const float*)d_in[6];
    const float* W1         = (const float*)d_in[7];
    const float* W2         = (const float*)d_in[8];
    const float* W3         = (const float*)d_in[9];
    const float* W4         = (const float*)d_in[10];
    const float* Wds        = (const float*)d_in[11];
    const float* Wdv        = (const float*)d_in[12];
    const float* Wsc        = (const float*)d_in[13];
    const float* Wps        = (const float*)d_in[14];
    const float* Wpv        = (const float*)d_in[15];
    const float* Wout       = (const float*)d_in[16];
    const int*   species    = (const int*)d_in[17];
    const int*   senders    = (const int*)d_in[18];
    const int*   receivers  = (const int*)d_in[19];
    float* out = (float*)d_out;

    const int MLP_SMEM  = MLP_SMEM_FLOATS * 4;    // 195584 B
    const int POST_SMEM = POST_SMEM_FLOATS * 4;   // 83968 B
    cudaFuncSetAttribute(mlp_kernel, cudaFuncAttributeMaxDynamicSharedMemorySize, MLP_SMEM);
    cudaFuncSetAttribute(node_post,  cudaFuncAttributeMaxDynamicSharedMemorySize, POST_SMEM);

    zero_agg<<<2048, 256>>>();
    node_pre<<<444, 512>>>(node_feats, Wss, Wsv, Wus, Wuv, species);
    mlp_kernel<<<EE/256, 512, MLP_SMEM>>>(re, W1, W2, W3, W4);
    tp_scatter<<<EE*64/256, 256>>>(vectors, senders, receivers);
    node_post<<<296, 512, POST_SMEM>>>(Wds, Wdv, Wsc, Wps, Wpv, Wout, species, out);
}

// round 14
// speedup vs baseline: 1.1033x; 1.0021x over previous
#include <cuda_runtime.h>
#include <cuda_fp16.h>
#include <math.h>

#define NN 32768
#define EE 262144
#define FF 64
#define PSC 9
#define ZZ 10
#define NF (NN*FF)
#define HS 68   // padded row stride (floats)

typedef unsigned long long u64;

// ---------------- device scratch ----------------
__device__ float g_skip_s[NF];
__device__ float g_skip_v[3*NF];
__device__ float g_sup[NF];
__device__ float g_vup[3*NF];
__device__ float g_agg_s[NF];
__device__ float g_agg_v[3*NF];
__device__ __half g_wh[(size_t)EE*320];   // per-edge TP path weights [E,5,64], fp16
__device__ __half g_wssh[ZZ*4096];        // fp16 per-species skip weights
__device__ __half g_wsvh[ZZ*4096];

// ---------------- f32x2 packed-math helpers ----------------
__device__ __forceinline__ u64 pack2(float x) {
    u64 r; asm("mov.b64 %0, {%1, %1};" : "=l"(r) : "f"(x)); return r;
}
__device__ __forceinline__ u64 fma2(u64 a, u64 b, u64 c) {
    u64 d; asm("fma.rn.f32x2 %0, %1, %2, %3;" : "=l"(d) : "l"(a), "l"(b), "l"(c)); return d;
}
__device__ __forceinline__ float2 unpk(u64 a) {
    float2 f; asm("mov.b64 {%0, %1}, %2;" : "=f"(f.x), "=f"(f.y) : "l"(a)); return f;
}
__device__ __forceinline__ float silu(float x) { return x / (1.f + __expf(-x)); }

__global__ void zero_agg() {
    int stride = gridDim.x * blockDim.x;
    int t = blockIdx.x * blockDim.x + threadIdx.x;
    for (int i = t; i < NF; i += stride) g_agg_s[i] = 0.f;
    for (int i = t; i < 3*NF; i += stride) g_agg_v[i] = 0.f;
}

// convert per-species skip weights to fp16 (320 KB total, trivial)
__global__ void convert_skip(const float* __restrict__ Wss, const float* __restrict__ Wsv) {
    int i = blockIdx.x * 256 + threadIdx.x;
    if (i < ZZ*4096) {
        g_wssh[i] = __float2half(Wss[i]);
        g_wsvh[i] = __float2half(Wsv[i]);
    }
}

// ---------------- kernel A: per-species skip linear (fp16 weights) + linear_up ----------------
__global__ void __launch_bounds__(512)
node_pre(const float* __restrict__ nf,
         const float* __restrict__ Wus,
         const float* __restrict__ Wuv,
         const int*   __restrict__ species) {
    __shared__ float sWus[FF*FF], sWuv[FF*FF];
    __shared__ float s_sh[8][FF];
    __shared__ float v_sh[8][3*FF];
    int tid = threadIdx.x;
    for (int i = tid; i < FF*FF; i += 512) { sWus[i] = Wus[i]; sWuv[i] = Wuv[i]; }
    __syncthreads();
    int g = tid & 63, grp = tid >> 6;
    int bar = grp + 1;
    int group_id = blockIdx.x * 8 + grp;
    int totalGroups = gridDim.x * 8;
    for (int n = group_id; n < NN; n += totalGroups) {
        const float* row = nf + (size_t)n * 256;
        s_sh[grp][g]        = row[g];
        v_sh[grp][g]        = row[64 + g];
        v_sh[grp][64 + g]   = row[128 + g];
        v_sh[grp][128 + g]  = row[192 + g];
        asm volatile("bar.sync %0, 64;" :: "r"(bar) : "memory");
        int z = species[n];
        const __half* wssz = g_wssh + z * 4096;
        const __half* wsvz = g_wsvh + z * 4096;
        float ks = 0.f, kv0 = 0.f, kv1 = 0.f, kv2 = 0.f;
        float us = 0.f, uv0 = 0.f, uv1 = 0.f, uv2 = 0.f;
        #pragma unroll 8
        for (int f = 0; f < FF; f++) {
            float sv = s_sh[grp][f];
            float a0 = v_sh[grp][f*3], a1 = v_sh[grp][f*3+1], a2 = v_sh[grp][f*3+2];
            float w1 = __half2float(__ldg(wssz + f*64 + g));
            float w2 = __half2float(__ldg(wsvz + f*64 + g));
            float w3 = sWus[f*64 + g];
            float w4 = sWuv[f*64 + g];
            ks  += sv * w1; kv0 += a0 * w2; kv1 += a1 * w2; kv2 += a2 * w2;
            us  += sv * w3; uv0 += a0 * w4; uv1 += a1 * w4; uv2 += a2 * w4;
        }
        const float invZ = 0.039528471f;
        const float inv  = 0.125f;
        g_skip_s[n*64 + g]          = ks  * invZ;
        g_skip_v[0*NF + n*64 + g]   = kv0 * invZ;
        g_skip_v[1*NF + n*64 + g]   = kv1 * invZ;
        g_skip_v[2*NF + n*64 + g]   = kv2 * invZ;
        g_sup[n*64 + g]             = us  * inv;
        g_vup[0*NF + n*64 + g]      = uv0 * inv;
        g_vup[1*NF + n*64 + g]      = uv1 * inv;
        g_vup[2*NF + n*64 + g]      = uv2 * inv;
        asm volatile("bar.sync %0, 64;" :: "r"(bar) : "memory");
    }
}

// ---------------- kernel B1: radial MLP (R13 core, unroll 8) ----------------
#define MLP_SMEM_FLOATS (512 + 4096 + 4096 + 20480 + 2048 + 256*HS)

__device__ __forceinline__ void kstep(const float* __restrict__ hin, int e0, int k,
                                      const float* __restrict__ wrow, u64 acc[4][4]) {
    u64 hp[4];
    #pragma unroll
    for (int ee = 0; ee < 4; ee++) hp[ee] = pack2(hin[(e0+ee)*HS + k]);
    ulonglong2 wa = *(const ulonglong2*)(wrow);
    ulonglong2 wb = *(const ulonglong2*)(wrow + 4);
    #pragma unroll
    for (int ee = 0; ee < 4; ee++) {
        acc[0][ee] = fma2(hp[ee], wa.x, acc[0][ee]);
        acc[1][ee] = fma2(hp[ee], wa.y, acc[1][ee]);
        acc[2][ee] = fma2(hp[ee], wb.x, acc[2][ee]);
        acc[3][ee] = fma2(hp[ee], wb.y, acc[3][ee]);
    }
}

__device__ __forceinline__ void zacc(u64 acc[4][4]) {
    #pragma unroll
    for (int gp = 0; gp < 4; gp++)
        #pragma unroll
        for (int ee = 0; ee < 4; ee++) acc[gp][ee] = 0ull;
}

__device__ __forceinline__ void write_silu(u64 acc[4][4], float* h, int e0, int g0, float scale) {
    #pragma unroll
    for (int ee = 0; ee < 4; ee++) {
        float2 a = unpk(acc[0][ee]), b = unpk(acc[1][ee]);
        float2 c = unpk(acc[2][ee]), d = unpk(acc[3][ee]);
        float4 lo = make_float4(silu(a.x*scale), silu(a.y*scale), silu(b.x*scale), silu(b.y*scale));
        float4 hi = make_float4(silu(c.x*scale), silu(c.y*scale), silu(d.x*scale), silu(d.y*scale));
        *(float4*)(h + (e0+ee)*HS + g0)     = lo;
        *(float4*)(h + (e0+ee)*HS + g0 + 4) = hi;
    }
}

__global__ void __launch_bounds__(512)
mlp_kernel(const float* __restrict__ re,
           const float* __restrict__ W1,
           const float* __restrict__ W2,
           const float* __restrict__ W3,
           const float* __restrict__ W4) {
    extern __shared__ float sm[];
    float* sW1 = sm;
    float* sW2 = sW1 + 512;
    float* sW3 = sW2 + 4096;
    float* sW4 = sW3 + 4096;
    float* sRE = sW4 + 20480;
    float* h   = sRE + 2048;
    int tid = threadIdx.x;
    for (int i = tid; i < 512;   i += 512) sW1[i] = W1[i];
    for (int i = tid; i < 4096;  i += 512) { sW2[i] = W2[i]; sW3[i] = W3[i]; }
    for (int i = tid; i < 20480; i += 512) sW4[i] = W4[i];

    int e_base = blockIdx.x * 256;
    for (int i = tid; i < 2048; i += 512) sRE[i] = re[(size_t)e_base*8 + i];
    __syncthreads();

    int cj = tid & 7, ei = tid >> 3;
    int g0 = cj * 8, e0 = ei * 4;

    u64 acc[4][4];

    zacc(acc);
    #pragma unroll
    for (int k = 0; k < 8; k++) {
        u64 hp[4];
        #pragma unroll
        for (int ee = 0; ee < 4; ee++) hp[ee] = pack2(sRE[(e0+ee)*8 + k]);
        ulonglong2 wa = *(const ulonglong2*)(sW1 + k*64 + g0);
        ulonglong2 wb = *(const ulonglong2*)(sW1 + k*64 + g0 + 4);
        #pragma unroll
        for (int ee = 0; ee < 4; ee++) {
            acc[0][ee] = fma2(hp[ee], wa.x, acc[0][ee]);
            acc[1][ee] = fma2(hp[ee], wa.y, acc[1][ee]);
            acc[2][ee] = fma2(hp[ee], wb.x, acc[2][ee]);
            acc[3][ee] = fma2(hp[ee], wb.y, acc[3][ee]);
        }
    }
    write_silu(acc, h, e0, g0, 0.35355339f);
    __syncthreads();

    zacc(acc);
    #pragma unroll 8
    for (int k = 0; k < 64; k++) kstep(h, e0, k, sW2 + k*64 + g0, acc);
    __syncthreads();
    write_silu(acc, h, e0, g0, 0.125f);
    __syncthreads();

    zacc(acc);
    #pragma unroll 8
    for (int k = 0; k < 64; k++) kstep(h, e0, k, sW3 + k*64 + g0, acc);
    __syncthreads();
    write_silu(acc, h, e0, g0, 0.125f);
    __syncthreads();

    // layer 4: 5 path slices of W4, write g_wh (fp16)
    #pragma unroll
    for (int p = 0; p < 5; p++) {
        zacc(acc);
        #pragma unroll 8
        for (int k = 0; k < 64; k++) kstep(h, e0, k, sW4 + k*320 + p*64 + g0, acc);
        #pragma unroll
        for (int ee = 0; ee < 4; ee++) {
            float2 a = unpk(acc[0][ee]), b = unpk(acc[1][ee]);
            float2 c = unpk(acc[2][ee]), d = unpk(acc[3][ee]);
            __half2 h0 = __floats2half2_rn(a.x*0.125f, a.y*0.125f);
            __half2 h1 = __floats2half2_rn(b.x*0.125f, b.y*0.125f);
            __half2 h2 = __floats2half2_rn(c.x*0.125f, c.y*0.125f);
            __half2 h3 = __floats2half2_rn(d.x*0.125f, d.y*0.125f);
            __half2* dst = (__half2*)(g_wh + (size_t)(e_base + e0 + ee)*320 + p*64 + g0);
            uint4 pk;
            pk.x = *(unsigned*)&h0; pk.y = *(unsigned*)&h1;
            pk.z = *(unsigned*)&h2; pk.w = *(unsigned*)&h3;
            *(uint4*)dst = pk;
        }
    }
}

// ---------------- kernel B2: tensor product + scatter (R13 exact) ----------------
__global__ void tp_scatter(const float* __restrict__ vectors,
                           const int* __restrict__ senders,
                           const int* __restrict__ receivers) {
    int t = blockIdx.x * 256 + threadIdx.x;
    int e = t >> 6, g = t & 63;
    float vx = __ldg(vectors + e*3), vy = __ldg(vectors + e*3 + 1), vz = __ldg(vectors + e*3 + 2);
    float rn = 1.f / (sqrtf(vx*vx + vy*vy + vz*vz) + 1e-9f);
    float y0 = vx * rn, y1 = vy * rn, y2 = vz * rn;

    const __half* wrow = g_wh + (size_t)e*320 + g;
    float w0  = __half2float(wrow[0]);
    float w1a = __half2float(wrow[64]);
    float w2a = __half2float(wrow[128]);
    float w3a = __half2float(wrow[192]);
    float w4a = __half2float(wrow[256]);

    int sn = __ldg(senders + e), rc = __ldg(receivers + e);
    float ss = g_sup[sn*64 + g];
    float b0 = g_vup[0*NF + sn*64 + g];
    float b1 = g_vup[1*NF + sn*64 + g];
    float b2 = g_vup[2*NF + sn*64 + g];
    float dot = b0*y0 + b1*y1 + b2*y2;
    float c0 = b1*y2 - b2*y1;
    float c1 = b2*y0 - b0*y2;
    float c2 = b0*y1 - b1*y0;
    const float is2 = 0.70710678f;
    float ms  = (w0*ss + w3a*dot) * 0.25f;
    float mv0 = (w1a*y0 + w2a*b0 + w4a*c0*is2) * 0.25f;
    float mv1 = (w1a*y1 + w2a*b1 + w4a*c1*is2) * 0.25f;
    float mv2 = (w1a*y2 + w2a*b2 + w4a*c2*is2) * 0.25f;
    atomicAdd(&g_agg_s[rc*64 + g], ms);
    atomicAdd(&g_agg_v[0*NF + rc*64 + g], mv0);
    atomicAdd(&g_agg_v[1*NF + rc*64 + g], mv1);
    atomicAdd(&g_agg_v[2*NF + rc*64 + g], mv2);
}

// ---------------- kernel C: node_post (R8 exact, 512 thr) ----------------
#define POST_SMEM_FLOATS (4*4096 + 8*576)
__global__ void __launch_bounds__(512)
node_post(const float* __restrict__ Wds,
          const float* __restrict__ Wdv,
          const float* __restrict__ Wsc,
          const float* __restrict__ Wps,
          const float* __restrict__ Wpv,
          const float* __restrict__ Wout,
          const int*   __restrict__ species,
          float* __restrict__ out) {
    extern __shared__ float sm[];
    float* sWds = sm;
    float* sWdv = sm + 4096;
    float* sWps = sm + 8192;
    float* sWpv = sm + 12288;
    float* buf  = sm + 16384;
    int tid = threadIdx.x;
    for (int i = tid; i < 4096; i += 512) {
        sWds[i] = Wds[i]; sWdv[i] = Wdv[i]; sWps[i] = Wps[i]; sWpv[i] = Wpv[i];
    }
    __syncthreads();
    int g = tid & 63, grp = tid >> 6, bar = grp + 1;
    float* ags = buf + grp * 576;
    float* agv = ags + 64;
    float* so  = agv + 192;
    float* vo  = so + 64;
    float* red = vo + 192;
    int group_id = blockIdx.x * 8 + grp;
    int totalGroups = gridDim.x * 8;
    for (int n = group_id; n < NN; n += totalGroups) {
        ags[g]       = g_agg_s[n*64 + g];
        agv[g]       = g_agg_v[0*NF + n*64 + g];
        agv[64 + g]  = g_agg_v[1*NF + n*64 + g];
        agv[128 + g] = g_agg_v[2*NF + n*64 + g];
        asm volatile("bar.sync %0, 64;" :: "r"(bar) : "memory");

        float sd = 0.f, vd0 = 0.f, vd1 = 0.f, vd2 = 0.f;
        #pragma unroll 8
        for (int f = 0; f < 64; f++) {
            float a  = ags[f];
            float a0 = agv[f], a1 = agv[64 + f], a2 = agv[128 + f];
            float w1 = sWds[f*64 + g], w2 = sWdv[f*64 + g];
            sd += a * w1; vd0 += a0 * w2; vd1 += a1 * w2; vd2 += a2 * w2;
        }
        sd *= 0.125f; vd0 *= 0.125f; vd1 *= 0.125f; vd2 *= 0.125f;

        int z = species[n];
        const float* wz = Wsc + z * (PSC*64) + g;
        float q0 = __ldg(wz),       q1 = __ldg(wz + 64),  q2 = __ldg(wz + 128);
        float q3 = __ldg(wz + 192), q4 = __ldg(wz + 256), q5 = __ldg(wz + 320);
        float q6 = __ldg(wz + 384), q7 = __ldg(wz + 448), q8 = __ldg(wz + 512);
        float vn2 = vd0*vd0 + vd1*vd1 + vd2*vd2;
        float s2  = sd * sd;
        float sout = q0*sd + q1*s2 + q2*vn2 + q3*s2*sd + q4*sd*vn2;
        float gv   = q5 + q6*sd + q7*s2 + q8*vn2;
        so[g] = sout;
        vo[g] = gv*vd0; vo[64 + g] = gv*vd1; vo[128 + g] = gv*vd2;
        asm volatile("bar.sync %0, 64;" :: "r"(bar) : "memory");

        float sp = 0.f, vp0 = 0.f, vp1 = 0.f, vp2 = 0.f;
        #pragma unroll 8
        for (int f = 0; f < 64; f++) {
            float a  = so[f];
            float a0 = vo[f], a1 = vo[64 + f], a2 = vo[128 + f];
            float w1 = sWps[f*64 + g], w2 = sWpv[f*64 + g];
            sp += a * w1; vp0 += a0 * w2; vp1 += a1 * w2; vp2 += a2 * w2;
        }
        sp  = sp  * 0.125f + g_skip_s[n*64 + g];
        vp0 = vp0 * 0.125f + g_skip_v[0*NF + n*64 + g];
        vp1 = vp1 * 0.125f + g_skip_v[1*NF + n*64 + g];
        vp2 = vp2 * 0.125f + g_skip_v[2*NF + n*64 + g];

        float* mrow = out + NN + (size_t)n * 256;
        mrow[g] = sp;
        mrow[64 + g*3]     = vp0;
        mrow[64 + g*3 + 1] = vp1;
        mrow[64 + g*3 + 2] = vp2;

        red[g] = sp * __ldg(Wout + g);
        asm volatile("bar.sync %0, 64;" :: "r"(bar) : "memory");
        if (g == 0) {
            float t2 = 0.f;
            #pragma unroll
            for (int i = 0; i < 64; i++) t2 += red[i];
            out[n] = t2 * 0.125f;
        }
        asm volatile("bar.sync %0, 64;" :: "r"(bar) : "memory");
    }
}

// ---------------- launch ----------------
extern "C" void kernel_launch(void* const* d_in, const int* in_sizes, int n_in,
                              void* d_out, int out_size) {
    const float* vectors    = (const float*)d_in[0];
    const float* node_feats = (const float*)d_in[1];
    const float* re         = (const float*)d_in[2];
    const float* Wss        = (const float*)d_in[3];
    const float* Wsv        = (const float*)d_in[4];
    const float* Wus        = (const float*)d_in[5];
    const float* Wuv        = (const float*)d_in[6];
    const float* W1         = (const float*)d_in[7];
    const float* W2         = (const float*)d_in[8];
    const float* W3         = (const float*)d_in[9];
    const float* W4         = (const float*)d_in[10];
    const float* Wds        = (const float*)d_in[11];
    const float* Wdv        = (const float*)d_in[12];
    const float* Wsc        = (const float*)d_in[13];
    const float* Wps        = (const float*)d_in[14];
    const float* Wpv        = (const float*)d_in[15];
    const float* Wout       = (const float*)d_in[16];
    const int*   species    = (const int*)d_in[17];
    const int*   senders    = (const int*)d_in[18];
    const int*   receivers  = (const int*)d_in[19];
    float* out = (float*)d_out;

    const int MLP_SMEM  = MLP_SMEM_FLOATS * 4;    // 195584 B
    const int POST_SMEM = POST_SMEM_FLOATS * 4;   // 83968 B
    cudaFuncSetAttribute(mlp_kernel, cudaFuncAttributeMaxDynamicSharedMemorySize, MLP_SMEM);
    cudaFuncSetAttribute(node_post,  cudaFuncAttributeMaxDynamicSharedMemorySize, POST_SMEM);

    zero_agg<<<2048, 256>>>();
    convert_skip<<<(ZZ*4096 + 255)/256, 256>>>(Wss, Wsv);
    node_pre<<<444, 512>>>(node_feats, Wus, Wuv, species);
    mlp_kernel<<<EE/256, 512, MLP_SMEM>>>(re, W1, W2, W3, W4);
    tp_scatter<<<EE*64/256, 256>>>(vectors, senders, receivers);
    node_post<<<296, 512, POST_SMEM>>>(Wds, Wdv, Wsc, Wps, Wpv, Wout, species, out);
}